// round 3
// baseline (speedup 1.0000x reference)
#include <cuda_runtime.h>
#include <math.h>
#include <stddef.h>

// ---------------- problem constants ----------------
#define VSZ   4000
#define ESZ   256
#define HSZ   256
#define MSZ   128
#define BSZ   32
#define LSEG  4
#define SSEG  126          // M-2
#define SB    (SSEG*BSZ)   // 4032
#define G4    (4*HSZ)      // 1024
#define NEGINF (-1.0e6f)

// ---------------- scratch (device globals; no allocation allowed) ----------------
__device__ float g_inputs [MSZ*BSZ*HSZ];      // (t,b,h) embedded tokens
__device__ float g_issing [MSZ*BSZ];          // -1e6 if token in {0,1,2}
__device__ float g_enc_xg [MSZ*BSZ*G4];       // inputs @ enc_Wih.T + bih + bhh
__device__ float g_enc_out[MSZ*BSZ*HSZ];      // 0.5 * h_t
__device__ float g_sos    [SB*HSZ];
__device__ float g_dxg0   [SB*G4];            // sos @ dec_Wih.T + biases
__device__ float g_vxg    [VSZ*G4];           // embedding @ dec_Wih.T + biases
__device__ float g_gates  [SB*G4];            // h @ dec_Whh.T (raw)
__device__ float g_dec_h  [SB*HSZ];
__device__ float g_dec_c  [SB*HSZ];
__device__ float g_dec_out[(LSEG+1)*SB*HSZ];  // (t, s*32+b, h)
__device__ float g_lse    [(LSEG+1)*SB];
__device__ float g_tgtlog [(LSEG+1)*SB];
__device__ float g_eoslog [(LSEG+1)*SB];
__device__ float g_logpy  [(SSEG+1)*LSEG*BSZ];  // (e, k, b)

__device__ __forceinline__ float sigmoidf(float x) { return 1.0f/(1.0f+expf(-x)); }

// ---------------- embed + is_single ----------------
__global__ void embed_kernel(const int* __restrict__ x, const float* __restrict__ emb,
                             float* __restrict__ inputs, float* __restrict__ issing)
{
    int row = blockIdx.x;                 // t*32+b, 4096 rows
    int t = row >> 5, b = row & 31;
    int tok = x[b*MSZ + t];
    const float4* src = (const float4*)(emb + (size_t)tok*ESZ);
    float4* dst = (float4*)(inputs + (size_t)row*ESZ);
    dst[threadIdx.x] = src[threadIdx.x];  // 64 threads x float4 = 256 floats
    if (threadIdx.x == 0)
        issing[row] = (tok == 0 || tok == 1 || tok == 2) ? NEGINF : 0.0f;
}

// ---------------- generic C = A @ W^T (+b1+b2) [tanh] ; K=256 ----------------
// epi: 0 = +bias, 1 = tanh(+bias), 2 = raw
__global__ __launch_bounds__(256)
void gemm_tn(const float* __restrict__ A, const float* __restrict__ W,
             const float* __restrict__ b1, const float* __restrict__ b2,
             float* __restrict__ C, int R, int N, int epi)
{
    const int K = 256;
    __shared__ float As[32][68];   // [k][m], pad keeps float4 alignment (68*4=272B)
    __shared__ float Ws[32][68];   // [k][n]
    int tid = threadIdx.x;
    int tx = tid & 15, ty = tid >> 4;
    int m0 = blockIdx.y * 64, n0 = blockIdx.x * 64;

    float acc[4][4];
#pragma unroll
    for (int i = 0; i < 4; i++)
#pragma unroll
        for (int j = 0; j < 4; j++) acc[i][j] = 0.0f;

    for (int kc = 0; kc < K; kc += 32) {
#pragma unroll
        for (int l = 0; l < 2; l++) {
            int slot = tid + l*256;     // 0..511 float4 slots
            int row  = slot >> 3;       // 0..63
            int c4   = slot & 7;        // 0..7
            float4 av = make_float4(0,0,0,0), wv = make_float4(0,0,0,0);
            if (m0 + row < R) av = *(const float4*)(A + (size_t)(m0+row)*K + kc + c4*4);
            if (n0 + row < N) wv = *(const float4*)(W + (size_t)(n0+row)*K + kc + c4*4);
            As[c4*4+0][row] = av.x; As[c4*4+1][row] = av.y;
            As[c4*4+2][row] = av.z; As[c4*4+3][row] = av.w;
            Ws[c4*4+0][row] = wv.x; Ws[c4*4+1][row] = wv.y;
            Ws[c4*4+2][row] = wv.z; Ws[c4*4+3][row] = wv.w;
        }
        __syncthreads();
#pragma unroll
        for (int k = 0; k < 32; k++) {
            float4 a4 = *(const float4*)&As[k][ty*4];
            float4 b4 = *(const float4*)&Ws[k][tx*4];
            float ar[4] = {a4.x, a4.y, a4.z, a4.w};
            float br[4] = {b4.x, b4.y, b4.z, b4.w};
#pragma unroll
            for (int i = 0; i < 4; i++)
#pragma unroll
                for (int j = 0; j < 4; j++) acc[i][j] += ar[i]*br[j];
        }
        __syncthreads();
    }
#pragma unroll
    for (int i = 0; i < 4; i++) {
        int r = m0 + ty*4 + i;
        if (r >= R) continue;
#pragma unroll
        for (int j = 0; j < 4; j++) {
            int n = n0 + tx*4 + j;
            if (n >= N) continue;
            float v = acc[i][j];
            if (epi != 2) { v += b1[n]; if (b2) v += b2[n]; }
            if (epi == 1) v = tanhf(v);
            C[(size_t)r*N + n] = v;
        }
    }
}

// ---------------- encoder: one block per batch element, 128 serial steps ----------------
__global__ __launch_bounds__(256)
void enc_lstm(const float* __restrict__ xg, const float* __restrict__ Whh,
              const float* __restrict__ h0, const float* __restrict__ c0,
              float* __restrict__ enc_out)
{
    int b = blockIdx.x, tid = threadIdx.x;        // 256 threads
    __shared__ float hsh[HSZ];
    hsh[tid] = h0[tid];
    float c = c0[tid];
    const float* w_i = Whh + (size_t)(tid      )*HSZ;
    const float* w_f = Whh + (size_t)(tid + 256)*HSZ;
    const float* w_g = Whh + (size_t)(tid + 512)*HSZ;
    const float* w_o = Whh + (size_t)(tid + 768)*HSZ;
    __syncthreads();

    for (int t = 0; t < MSZ; t++) {
        const float* xr = xg + ((size_t)t*BSZ + b)*G4;
        float gi = xr[tid], gf = xr[tid+256], gg = xr[tid+512], go = xr[tid+768];
#pragma unroll 4
        for (int k = 0; k < HSZ; k += 4) {
            float4 h4  = *(const float4*)&hsh[k];
            float4 wi4 = *(const float4*)(w_i + k);
            float4 wf4 = *(const float4*)(w_f + k);
            float4 wg4 = *(const float4*)(w_g + k);
            float4 wo4 = *(const float4*)(w_o + k);
            gi += h4.x*wi4.x + h4.y*wi4.y + h4.z*wi4.z + h4.w*wi4.w;
            gf += h4.x*wf4.x + h4.y*wf4.y + h4.z*wf4.z + h4.w*wf4.w;
            gg += h4.x*wg4.x + h4.y*wg4.y + h4.z*wg4.z + h4.w*wg4.w;
            go += h4.x*wo4.x + h4.y*wo4.y + h4.z*wo4.z + h4.w*wo4.w;
        }
        float cn = sigmoidf(gf)*c + sigmoidf(gi)*tanhf(gg);
        float hn = sigmoidf(go)*tanhf(cn);
        c = cn;
        __syncthreads();
        hsh[tid] = hn;
        enc_out[((size_t)t*BSZ + b)*HSZ + tid] = 0.5f*hn;
        __syncthreads();
    }
}

// ---------------- decoder pointwise (gather input gates by token id) ----------------
__global__ void dec_point(const float* __restrict__ gates, const float* __restrict__ xg0,
                          const float* __restrict__ vxg, const int* __restrict__ x,
                          const float* __restrict__ bih, const float* __restrict__ bhh,
                          float* __restrict__ h, float* __restrict__ cc,
                          float* __restrict__ dec_out, int t)
{
    int r = blockIdx.x, j = threadIdx.x;   // r = s*32+b
    int s = r >> 5, b = r & 31;
    const float* base = nullptr;
    if (t == 0) base = xg0 + (size_t)r*G4;
    else {
        int pos = s + t;                    // dec_in[t] = pad_in[s+t]
        if (pos <= MSZ-1) base = vxg + (size_t)x[b*MSZ + pos]*G4;
    }
    float xi, xf, xgv, xo;
    if (base) { xi = base[j]; xf = base[j+256]; xgv = base[j+512]; xo = base[j+768]; }
    else {     xi = bih[j]+bhh[j]; xf = bih[j+256]+bhh[j+256];
               xgv = bih[j+512]+bhh[j+512]; xo = bih[j+768]+bhh[j+768]; }
    const float* gr = gates + (size_t)r*G4;
    float gi = gr[j] + xi, gf = gr[j+256] + xf, gg = gr[j+512] + xgv, go = gr[j+768] + xo;
    float cp = (t == 0) ? 0.0f : cc[(size_t)r*HSZ + j];
    float cn = sigmoidf(gf)*cp + sigmoidf(gi)*tanhf(gg);
    float hn = sigmoidf(go)*tanhf(cn);
    cc[(size_t)r*HSZ + j] = cn;
    h [(size_t)r*HSZ + j] = hn;
    dec_out[((size_t)t*SB + r)*HSZ + j] = hn;
}

// ---------------- fused logits GEMM + online LSE + target/EOS extraction ----------------
__global__ __launch_bounds__(256)
void logits_lse(const float* __restrict__ dout, const float* __restrict__ emb,
                const float* __restrict__ e2vb, const int* __restrict__ x,
                float* __restrict__ lse, float* __restrict__ tgtlog,
                float* __restrict__ eoslog)
{
    __shared__ float As[32][68];
    __shared__ float Ws[32][68];
    __shared__ float redm[64][17];
    __shared__ float reds[64][17];
    int tid = threadIdx.x, tx = tid & 15, ty = tid >> 4;
    int row0 = blockIdx.x * 64;           // rows = t*4032 + s*32 + b, total 20160 (315 blocks)

    // per-thread: target vocab ids for its 4 rows
    int vt[4];
#pragma unroll
    for (int i = 0; i < 4; i++) {
        int row = row0 + ty*4 + i;
        int t = row / SB; int r = row % SB; int s = r >> 5; int b = r & 31;
        if (t < LSEG) { int pos = s + 1 + t; vt[i] = (pos <= MSZ-1) ? x[b*MSZ + pos] : 0; }
        else vt[i] = -1;
    }
    float mM[4], sS[4];
#pragma unroll
    for (int i = 0; i < 4; i++) { mM[i] = -3.0e38f; sS[i] = 0.0f; }

    for (int v0 = 0; v0 < VSZ; v0 += 64) {
        float acc[4][4];
#pragma unroll
        for (int i = 0; i < 4; i++)
#pragma unroll
            for (int j = 0; j < 4; j++) acc[i][j] = 0.0f;

        for (int kc = 0; kc < 256; kc += 32) {
#pragma unroll
            for (int l = 0; l < 2; l++) {
                int slot = tid + l*256; int row = slot >> 3; int c4 = slot & 7;
                float4 av = *(const float4*)(dout + (size_t)(row0+row)*HSZ + kc + c4*4);
                int v = v0 + row;
                float4 wv = (v < VSZ) ? *(const float4*)(emb + (size_t)v*ESZ + kc + c4*4)
                                      : make_float4(0,0,0,0);
                As[c4*4+0][row] = av.x; As[c4*4+1][row] = av.y;
                As[c4*4+2][row] = av.z; As[c4*4+3][row] = av.w;
                Ws[c4*4+0][row] = wv.x; Ws[c4*4+1][row] = wv.y;
                Ws[c4*4+2][row] = wv.z; Ws[c4*4+3][row] = wv.w;
            }
            __syncthreads();
#pragma unroll
            for (int k = 0; k < 32; k++) {
                float4 a4 = *(const float4*)&As[k][ty*4];
                float4 b4 = *(const float4*)&Ws[k][tx*4];
                float ar[4] = {a4.x, a4.y, a4.z, a4.w};
                float br[4] = {b4.x, b4.y, b4.z, b4.w};
#pragma unroll
                for (int i = 0; i < 4; i++)
#pragma unroll
                    for (int j = 0; j < 4; j++) acc[i][j] += ar[i]*br[j];
            }
            __syncthreads();
        }
        // online LSE update + selective extraction for this v-tile
#pragma unroll
        for (int j = 0; j < 4; j++) {
            int v = v0 + tx*4 + j;
            if (v >= VSZ) continue;
            float bias = e2vb[v];
#pragma unroll
            for (int i = 0; i < 4; i++) {
                float lv = acc[i][j] + bias;
                float nm = fmaxf(mM[i], lv);
                sS[i] = sS[i]*expf(mM[i]-nm) + expf(lv-nm);
                mM[i] = nm;
                int row = row0 + ty*4 + i;
                if (v == vt[i]) tgtlog[row] = lv;
                if (v == 3)     eoslog[row] = lv;   // EOS
            }
        }
    }
    __syncthreads();
#pragma unroll
    for (int i = 0; i < 4; i++) { redm[ty*4+i][tx] = mM[i]; reds[ty*4+i][tx] = sS[i]; }
    __syncthreads();
    if (tid < 64) {
        float m = redm[tid][0], s = reds[tid][0];
#pragma unroll
        for (int q = 1; q < 16; q++) {
            float m2 = redm[tid][q], s2 = reds[tid][q];
            float nm = fmaxf(m, m2);
            s = s*expf(m-nm) + s2*expf(m2-nm);
            m = nm;
        }
        lse[row0 + tid] = m + logf(s);
    }
}

// ---------------- segment log-probs -> logpy table ----------------
__global__ void logpy_kernel(const float* __restrict__ lse, const float* __restrict__ tgtlog,
                             const float* __restrict__ eoslog, const float* __restrict__ issing,
                             float* __restrict__ logpy)
{
    int idx = blockIdx.x*blockDim.x + threadIdx.x;   // (e,b)
    if (idx >= (SSEG+1)*BSZ) return;
    int e = idx >> 5, b = idx & 31;
    if (e == 0) {
        logpy[b] = 0.0f;
        for (int k = 1; k < LSEG; k++) logpy[k*BSZ + b] = NEGINF;
        return;
    }
    int s = e - 1;
    int r = s*BSZ + b;
    float cum = 0.0f;
    float is_start = issing[(s+1)*BSZ + b];
    int jlen = SSEG - s; if (jlen > LSEG) jlen = LSEG;   // min(4, 126-s)
    for (int k = 0; k < LSEG; k++) {
        int rowk = k*SB + r;
        float tlp = tgtlog[rowk] - lse[rowk];
        float segis = ((s+1+k) <= MSZ-1) ? issing[(s+1+k)*BSZ + b] : 0.0f;
        cum += tlp + ((k >= 1) ? segis : 0.0f);
        int rowe = (k+1)*SB + r;
        float eos = eoslog[rowe] - lse[rowe];
        float val = cum + ((k >= 1) ? is_start : 0.0f) + eos;
        if (k >= jlen) val = NEGINF;
        logpy[(e*LSEG + k)*BSZ + b] = val;
    }
}

// ---------------- final DP over segmentations ----------------
__global__ void dp_kernel(const float* __restrict__ logpy, const int* __restrict__ lengths,
                          float* __restrict__ out)
{
    int b = threadIdx.x;                        // 32 threads
    __shared__ float alph[MSZ-1][BSZ];          // 127 x 32
    float buf[LSEG] = {0.0f, NEGINF, NEGINF, NEGINF};
    alph[0][b] = 0.0f;
    for (int m = 1; m < MSZ-1; m++) {
        float v[LSEG], mx = -3.0e38f;
#pragma unroll
        for (int k = 0; k < LSEG; k++) {
            int e = m - k;
            float slp = (e >= 1) ? logpy[(e*LSEG + k)*BSZ + b] : NEGINF;
            v[k] = buf[k] + slp;
            mx = fmaxf(mx, v[k]);
        }
        float ssum = 0.0f;
#pragma unroll
        for (int k = 0; k < LSEG; k++) ssum += expf(v[k]-mx);
        float a = mx + logf(ssum);
        buf[3] = buf[2]; buf[2] = buf[1]; buf[1] = buf[0]; buf[0] = a;
        alph[m][b] = a;
    }
    int Lb = lengths[b];
    float nll = -alph[Lb-2][b];
    float tlen = (float)Lb;
#pragma unroll
    for (int off = 16; off; off >>= 1) {
        nll  += __shfl_down_sync(0xffffffffu, nll,  off);
        tlen += __shfl_down_sync(0xffffffffu, tlen, off);
    }
    if (b == 0) out[0] = nll / (tlen - 2.0f*BSZ);
}

// ---------------- launch ----------------
extern "C" void kernel_launch(void* const* d_in, const int* in_sizes, int n_in,
                              void* d_out, int out_size)
{
    const int*   x        = (const int*)  d_in[0];
    const int*   lengths  = (const int*)  d_in[1];
    const float* emb      = (const float*)d_in[2];
    const float* e2vb     = (const float*)d_in[3];
    const float* enc_Wih  = (const float*)d_in[4];
    const float* enc_Whh  = (const float*)d_in[5];
    const float* enc_bih  = (const float*)d_in[6];
    const float* enc_bhh  = (const float*)d_in[7];
    const float* enc_h0   = (const float*)d_in[8];
    const float* enc_c0   = (const float*)d_in[9];
    const float* dec_Wih  = (const float*)d_in[10];
    const float* dec_Whh  = (const float*)d_in[11];
    const float* dec_bih  = (const float*)d_in[12];
    const float* dec_bhh  = (const float*)d_in[13];
    const float* dht_W    = (const float*)d_in[14];
    const float* dht_b    = (const float*)d_in[15];
    const float* sos_W    = (const float*)d_in[16];
    const float* sos_b    = (const float*)d_in[17];
    float* out = (float*)d_out;

    float *p_inputs, *p_issing, *p_enc_xg, *p_enc_out, *p_sos, *p_dxg0, *p_vxg;
    float *p_gates, *p_dec_h, *p_dec_c, *p_dec_out, *p_lse, *p_tgt, *p_eos, *p_logpy;
    cudaGetSymbolAddress((void**)&p_inputs,  g_inputs);
    cudaGetSymbolAddress((void**)&p_issing,  g_issing);
    cudaGetSymbolAddress((void**)&p_enc_xg,  g_enc_xg);
    cudaGetSymbolAddress((void**)&p_enc_out, g_enc_out);
    cudaGetSymbolAddress((void**)&p_sos,     g_sos);
    cudaGetSymbolAddress((void**)&p_dxg0,    g_dxg0);
    cudaGetSymbolAddress((void**)&p_vxg,     g_vxg);
    cudaGetSymbolAddress((void**)&p_gates,   g_gates);
    cudaGetSymbolAddress((void**)&p_dec_h,   g_dec_h);
    cudaGetSymbolAddress((void**)&p_dec_c,   g_dec_c);
    cudaGetSymbolAddress((void**)&p_dec_out, g_dec_out);
    cudaGetSymbolAddress((void**)&p_lse,     g_lse);
    cudaGetSymbolAddress((void**)&p_tgt,     g_tgtlog);
    cudaGetSymbolAddress((void**)&p_eos,     g_eoslog);
    cudaGetSymbolAddress((void**)&p_logpy,   g_logpy);

    // 1. embed + is_single
    embed_kernel<<<MSZ*BSZ, 64>>>(x, emb, p_inputs, p_issing);
    // 2. encoder input gates: (4096,1024,256)
    gemm_tn<<<dim3(16, 64), 256>>>(p_inputs, enc_Wih, enc_bih, enc_bhh, p_enc_xg,
                                   MSZ*BSZ, G4, 0);
    // 3. encoder recurrence: 32 independent batch blocks
    enc_lstm<<<BSZ, 256>>>(p_enc_xg, enc_Whh, enc_h0, enc_c0, p_enc_out);
    // 4. sos = enc_prev @ sos_W.T + sos_b   (enc_prev = first 4032 rows of enc_out)
    gemm_tn<<<dim3(4, 63), 256>>>(p_enc_out, sos_W, sos_b, nullptr, p_sos, SB, HSZ, 0);
    // 5. dec_h0 = tanh(enc_prev @ dht_W.T + dht_b)
    gemm_tn<<<dim3(4, 63), 256>>>(p_enc_out, dht_W, dht_b, nullptr, p_dec_h, SB, HSZ, 1);
    // 6. vocab input gates: embedding @ dec_Wih.T + biases
    gemm_tn<<<dim3(16, 63), 256>>>(emb, dec_Wih, dec_bih, dec_bhh, p_vxg, VSZ, G4, 0);
    // 7. step-0 input gates from sos
    gemm_tn<<<dim3(16, 63), 256>>>(p_sos, dec_Wih, dec_bih, dec_bhh, p_dxg0, SB, G4, 0);
    // 8. decoder: 5 sequential steps
    for (int t = 0; t <= LSEG; t++) {
        gemm_tn<<<dim3(16, 63), 256>>>(p_dec_h, dec_Whh, nullptr, nullptr, p_gates,
                                       SB, G4, 2);
        dec_point<<<SB, 256>>>(p_gates, p_dxg0, p_vxg, x, dec_bih, dec_bhh,
                               p_dec_h, p_dec_c, p_dec_out, t);
    }
    // 9. fused logits + LSE + target/EOS logit extraction (20160 rows)
    logits_lse<<<(LSEG+1)*SB/64, 256>>>(p_dec_out, emb, e2vb, x, p_lse, p_tgt, p_eos);
    // 10. segment log-probs table
    logpy_kernel<<<((SSEG+1)*BSZ + 127)/128, 128>>>(p_lse, p_tgt, p_eos, p_issing, p_logpy);
    // 11. DP + reduction -> scalar
    dp_kernel<<<1, 32>>>(p_logpy, lengths, out);

    (void)in_sizes; (void)n_in; (void)out_size;
}

// round 8
// speedup vs baseline: 1.0811x; 1.0811x over previous
#include <cuda_runtime.h>
#include <math.h>
#include <stddef.h>

// ---------------- problem constants ----------------
#define VSZ   4000
#define ESZ   256
#define HSZ   256
#define MSZ   128
#define BSZ   32
#define LSEG  4
#define SSEG  126          // M-2
#define SB    (SSEG*BSZ)   // 4032
#define G4    (4*HSZ)      // 1024
#define NROWS ((LSEG+1)*SB) // 20160
#define VCH   4            // vocab chunks for logits
#define VCHW  (VSZ/VCH)    // 1000
#define NEGINF (-1.0e6f)

// ---------------- scratch (device globals; no allocation allowed) ----------------
__device__ float g_inputs [MSZ*BSZ*HSZ];
__device__ float g_issing [MSZ*BSZ];
__device__ float g_enc_xg [MSZ*BSZ*G4];
__device__ float g_enc_out[MSZ*BSZ*HSZ];
__device__ float g_sos    [SB*HSZ];
__device__ float g_dxg0   [SB*G4];
__device__ float g_vxg    [VSZ*G4];
__device__ float g_gates  [SB*G4];
__device__ float g_dec_h  [SB*HSZ];
__device__ float g_dec_c  [SB*HSZ];
__device__ float g_dec_out[(LSEG+1)*SB*HSZ];
__device__ float g_pm     [VCH*NROWS];   // partial max per vocab chunk
__device__ float g_ps     [VCH*NROWS];   // partial sum per vocab chunk
__device__ float g_lse    [NROWS];
__device__ float g_tgtlog [NROWS];
__device__ float g_eoslog [NROWS];
__device__ float g_logpy  [(SSEG+1)*LSEG*BSZ];

__device__ __forceinline__ float sigmoidf(float x) { return 1.0f/(1.0f+__expf(-x)); }

// ---------------- embed + is_single ----------------
__global__ void embed_kernel(const int* __restrict__ x, const float* __restrict__ emb,
                             float* __restrict__ inputs, float* __restrict__ issing)
{
    int row = blockIdx.x;                 // t*32+b, 4096 rows
    int t = row >> 5, b = row & 31;
    int tok = x[b*MSZ + t];
    const float4* src = (const float4*)(emb + (size_t)tok*ESZ);
    float4* dst = (float4*)(inputs + (size_t)row*ESZ);
    dst[threadIdx.x] = src[threadIdx.x];  // 64 threads x float4
    if (threadIdx.x == 0)
        issing[row] = (tok == 0 || tok == 1 || tok == 2) ? NEGINF : 0.0f;
}

// ---------------- generic C = A @ W^T (+b1+b2) [tanh] ; K=256 ----------------
// epi: 0 = +bias, 1 = tanh(+bias), 2 = raw
__global__ __launch_bounds__(256)
void gemm_tn(const float* __restrict__ A, const float* __restrict__ W,
             const float* __restrict__ b1, const float* __restrict__ b2,
             float* __restrict__ C, int R, int N, int epi)
{
    const int K = 256;
    __shared__ float As[32][68];
    __shared__ float Ws[32][68];
    int tid = threadIdx.x;
    int tx = tid & 15, ty = tid >> 4;
    int m0 = blockIdx.y * 64, n0 = blockIdx.x * 64;

    float acc[4][4];
#pragma unroll
    for (int i = 0; i < 4; i++)
#pragma unroll
        for (int j = 0; j < 4; j++) acc[i][j] = 0.0f;

    for (int kc = 0; kc < K; kc += 32) {
#pragma unroll
        for (int l = 0; l < 2; l++) {
            int slot = tid + l*256;
            int row  = slot >> 3;
            int c4   = slot & 7;
            float4 av = make_float4(0,0,0,0), wv = make_float4(0,0,0,0);
            if (m0 + row < R) av = *(const float4*)(A + (size_t)(m0+row)*K + kc + c4*4);
            if (n0 + row < N) wv = *(const float4*)(W + (size_t)(n0+row)*K + kc + c4*4);
            As[c4*4+0][row] = av.x; As[c4*4+1][row] = av.y;
            As[c4*4+2][row] = av.z; As[c4*4+3][row] = av.w;
            Ws[c4*4+0][row] = wv.x; Ws[c4*4+1][row] = wv.y;
            Ws[c4*4+2][row] = wv.z; Ws[c4*4+3][row] = wv.w;
        }
        __syncthreads();
#pragma unroll
        for (int k = 0; k < 32; k++) {
            float4 a4 = *(const float4*)&As[k][ty*4];
            float4 b4 = *(const float4*)&Ws[k][tx*4];
            float ar[4] = {a4.x, a4.y, a4.z, a4.w};
            float br[4] = {b4.x, b4.y, b4.z, b4.w};
#pragma unroll
            for (int i = 0; i < 4; i++)
#pragma unroll
                for (int j = 0; j < 4; j++) acc[i][j] += ar[i]*br[j];
        }
        __syncthreads();
    }
#pragma unroll
    for (int i = 0; i < 4; i++) {
        int r = m0 + ty*4 + i;
        if (r >= R) continue;
#pragma unroll
        for (int j = 0; j < 4; j++) {
            int n = n0 + tx*4 + j;
            if (n >= N) continue;
            float v = acc[i][j];
            if (epi != 2) { v += b1[n]; if (b2) v += b2[n]; }
            if (epi == 1) v = tanhf(v);
            C[(size_t)r*N + n] = v;
        }
    }
}

// ---------------- encoder: one block per batch element, 128 serial steps ----------------
__global__ __launch_bounds__(256)
void enc_lstm(const float* __restrict__ xg, const float* __restrict__ Whh,
              const float* __restrict__ h0, const float* __restrict__ c0,
              float* __restrict__ enc_out)
{
    int b = blockIdx.x, tid = threadIdx.x;
    __shared__ float hsh[HSZ];
    hsh[tid] = h0[tid];
    float c = c0[tid];
    const float* w_i = Whh + (size_t)(tid      )*HSZ;
    const float* w_f = Whh + (size_t)(tid + 256)*HSZ;
    const float* w_g = Whh + (size_t)(tid + 512)*HSZ;
    const float* w_o = Whh + (size_t)(tid + 768)*HSZ;
    __syncthreads();

    for (int t = 0; t < MSZ; t++) {
        const float* xr = xg + ((size_t)t*BSZ + b)*G4;
        float gi = xr[tid], gf = xr[tid+256], gg = xr[tid+512], go = xr[tid+768];
#pragma unroll 4
        for (int k = 0; k < HSZ; k += 4) {
            float4 h4  = *(const float4*)&hsh[k];
            float4 wi4 = *(const float4*)(w_i + k);
            float4 wf4 = *(const float4*)(w_f + k);
            float4 wg4 = *(const float4*)(w_g + k);
            float4 wo4 = *(const float4*)(w_o + k);
            gi += h4.x*wi4.x + h4.y*wi4.y + h4.z*wi4.z + h4.w*wi4.w;
            gf += h4.x*wf4.x + h4.y*wf4.y + h4.z*wf4.z + h4.w*wf4.w;
            gg += h4.x*wg4.x + h4.y*wg4.y + h4.z*wg4.z + h4.w*wg4.w;
            go += h4.x*wo4.x + h4.y*wo4.y + h4.z*wo4.z + h4.w*wo4.w;
        }
        float cn = sigmoidf(gf)*c + sigmoidf(gi)*tanhf(gg);
        float hn = sigmoidf(go)*tanhf(cn);
        c = cn;
        __syncthreads();
        hsh[tid] = hn;
        enc_out[((size_t)t*BSZ + b)*HSZ + tid] = 0.5f*hn;
        __syncthreads();
    }
}

// ---------------- decoder pointwise ----------------
__global__ void dec_point(const float* __restrict__ gates, const float* __restrict__ xg0,
                          const float* __restrict__ vxg, const int* __restrict__ x,
                          const float* __restrict__ bih, const float* __restrict__ bhh,
                          float* __restrict__ h, float* __restrict__ cc,
                          float* __restrict__ dec_out, int t)
{
    int r = blockIdx.x, j = threadIdx.x;
    int s = r >> 5, b = r & 31;
    const float* base = nullptr;
    if (t == 0) base = xg0 + (size_t)r*G4;
    else {
        int pos = s + t;
        if (pos <= MSZ-1) base = vxg + (size_t)x[b*MSZ + pos]*G4;
    }
    float xi, xf, xgv, xo;
    if (base) { xi = base[j]; xf = base[j+256]; xgv = base[j+512]; xo = base[j+768]; }
    else {     xi = bih[j]+bhh[j]; xf = bih[j+256]+bhh[j+256];
               xgv = bih[j+512]+bhh[j+512]; xo = bih[j+768]+bhh[j+768]; }
    const float* gr = gates + (size_t)r*G4;
    float gi = gr[j] + xi, gf = gr[j+256] + xf, gg = gr[j+512] + xgv, go = gr[j+768] + xo;
    float cp = (t == 0) ? 0.0f : cc[(size_t)r*HSZ + j];
    float cn = sigmoidf(gf)*cp + sigmoidf(gi)*tanhf(gg);
    float hn = sigmoidf(go)*tanhf(cn);
    cc[(size_t)r*HSZ + j] = cn;
    h [(size_t)r*HSZ + j] = hn;
    dec_out[((size_t)t*SB + r)*HSZ + j] = hn;
}

// ---------------- fused logits GEMM + partial online LSE per vocab chunk ----------------
// grid: (315 m-tiles, VCH vocab chunks). Each block: 64 rows x 1000 vocab.
__global__ __launch_bounds__(256)
void logits_part(const float* __restrict__ dout, const float* __restrict__ emb,
                 const float* __restrict__ e2vb, const int* __restrict__ x,
                 float* __restrict__ pm, float* __restrict__ ps,
                 float* __restrict__ tgtlog, float* __restrict__ eoslog)
{
    __shared__ float As[32][68];
    __shared__ float Ws[32][68];
    __shared__ float redm[64][17];
    __shared__ float reds[64][17];
    int tid = threadIdx.x, tx = tid & 15, ty = tid >> 4;
    int row0 = blockIdx.x * 64;
    int vc   = blockIdx.y;
    int vstart = vc * VCHW, vend = vstart + VCHW;

    // per-thread target vocab ids for its 4 rows
    int vt[4];
#pragma unroll
    for (int i = 0; i < 4; i++) {
        int row = row0 + ty*4 + i;
        int t = row / SB; int r = row % SB; int s = r >> 5; int b = r & 31;
        if (t < LSEG) { int pos = s + 1 + t; vt[i] = (pos <= MSZ-1) ? x[b*MSZ + pos] : 0; }
        else vt[i] = -1;
    }
    float mM[4], sS[4];
#pragma unroll
    for (int i = 0; i < 4; i++) { mM[i] = -1.0e30f; sS[i] = 0.0f; }

    for (int v0 = vstart; v0 < vend; v0 += 64) {
        float acc[4][4];
#pragma unroll
        for (int i = 0; i < 4; i++)
#pragma unroll
            for (int j = 0; j < 4; j++) acc[i][j] = 0.0f;

        for (int kc = 0; kc < 256; kc += 32) {
#pragma unroll
            for (int l = 0; l < 2; l++) {
                int slot = tid + l*256; int row = slot >> 3; int c4 = slot & 7;
                float4 av = *(const float4*)(dout + (size_t)(row0+row)*HSZ + kc + c4*4);
                int v = v0 + row;
                float4 wv = (v < vend) ? *(const float4*)(emb + (size_t)v*ESZ + kc + c4*4)
                                       : make_float4(0,0,0,0);
                As[c4*4+0][row] = av.x; As[c4*4+1][row] = av.y;
                As[c4*4+2][row] = av.z; As[c4*4+3][row] = av.w;
                Ws[c4*4+0][row] = wv.x; Ws[c4*4+1][row] = wv.y;
                Ws[c4*4+2][row] = wv.z; Ws[c4*4+3][row] = wv.w;
            }
            __syncthreads();
#pragma unroll
            for (int k = 0; k < 32; k++) {
                float4 a4 = *(const float4*)&As[k][ty*4];
                float4 b4 = *(const float4*)&Ws[k][tx*4];
                float ar[4] = {a4.x, a4.y, a4.z, a4.w};
                float br[4] = {b4.x, b4.y, b4.z, b4.w};
#pragma unroll
                for (int i = 0; i < 4; i++)
#pragma unroll
                    for (int j = 0; j < 4; j++) acc[i][j] += ar[i]*br[j];
            }
            __syncthreads();
        }
        // online LSE update (fast exp, rare-max branch) + selective extraction
#pragma unroll
        for (int j = 0; j < 4; j++) {
            int v = v0 + tx*4 + j;
            if (v >= vend) continue;
            float bias = e2vb[v];
#pragma unroll
            for (int i = 0; i < 4; i++) {
                float lv = acc[i][j] + bias;
                if (lv <= mM[i]) {
                    sS[i] += __expf(lv - mM[i]);
                } else {
                    sS[i] = sS[i]*__expf(mM[i] - lv) + 1.0f;
                    mM[i] = lv;
                }
                int row = row0 + ty*4 + i;
                if (v == vt[i]) tgtlog[row] = lv;
                if (v == 3)     eoslog[row] = lv;   // EOS (chunk 0 only)
            }
        }
    }
    __syncthreads();
#pragma unroll
    for (int i = 0; i < 4; i++) { redm[ty*4+i][tx] = mM[i]; reds[ty*4+i][tx] = sS[i]; }
    __syncthreads();
    if (tid < 64) {
        float m = redm[tid][0], s = reds[tid][0];
#pragma unroll
        for (int q = 1; q < 16; q++) {
            float m2 = redm[tid][q], s2 = reds[tid][q];
            if (m2 <= m) { s += s2*__expf(m2 - m); }
            else         { s = s*__expf(m - m2) + s2; m = m2; }
        }
        pm[(size_t)vc*NROWS + row0 + tid] = m;
        ps[(size_t)vc*NROWS + row0 + tid] = s;
    }
}

// ---------------- merge vocab-chunk partials -> final LSE ----------------
__global__ void lse_merge(const float* __restrict__ pm, const float* __restrict__ ps,
                          float* __restrict__ lse)
{
    int r = blockIdx.x*256 + threadIdx.x;
    if (r >= NROWS) return;
    float m = pm[r], s = ps[r];
#pragma unroll
    for (int c = 1; c < VCH; c++) {
        float m2 = pm[(size_t)c*NROWS + r], s2 = ps[(size_t)c*NROWS + r];
        if (m2 <= m) { s += s2*__expf(m2 - m); }
        else         { s = s*__expf(m - m2) + s2; m = m2; }
    }
    lse[r] = m + __logf(s);
}

// ---------------- segment log-probs -> logpy table ----------------
__global__ void logpy_kernel(const float* __restrict__ lse, const float* __restrict__ tgtlog,
                             const float* __restrict__ eoslog, const float* __restrict__ issing,
                             float* __restrict__ logpy)
{
    int idx = blockIdx.x*blockDim.x + threadIdx.x;
    if (idx >= (SSEG+1)*BSZ) return;
    int e = idx >> 5, b = idx & 31;
    if (e == 0) {
        logpy[b] = 0.0f;
        for (int k = 1; k < LSEG; k++) logpy[k*BSZ + b] = NEGINF;
        return;
    }
    int s = e - 1;
    int r = s*BSZ + b;
    float cum = 0.0f;
    float is_start = issing[(s+1)*BSZ + b];
    int jlen = SSEG - s; if (jlen > LSEG) jlen = LSEG;
    for (int k = 0; k < LSEG; k++) {
        int rowk = k*SB + r;
        float tlp = tgtlog[rowk] - lse[rowk];
        float segis = ((s+1+k) <= MSZ-1) ? issing[(s+1+k)*BSZ + b] : 0.0f;
        cum += tlp + ((k >= 1) ? segis : 0.0f);
        int rowe = (k+1)*SB + r;
        float eos = eoslog[rowe] - lse[rowe];
        float val = cum + ((k >= 1) ? is_start : 0.0f) + eos;
        if (k >= jlen) val = NEGINF;
        logpy[(e*LSEG + k)*BSZ + b] = val;
    }
}

// ---------------- final DP over segmentations ----------------
__global__ void dp_kernel(const float* __restrict__ logpy, const int* __restrict__ lengths,
                          float* __restrict__ out)
{
    int b = threadIdx.x;
    __shared__ float alph[MSZ-1][BSZ];
    float buf[LSEG] = {0.0f, NEGINF, NEGINF, NEGINF};
    alph[0][b] = 0.0f;
    for (int m = 1; m < MSZ-1; m++) {
        float v[LSEG], mx = -3.0e38f;
#pragma unroll
        for (int k = 0; k < LSEG; k++) {
            int e = m - k;
            float slp = (e >= 1) ? logpy[(e*LSEG + k)*BSZ + b] : NEGINF;
            v[k] = buf[k] + slp;
            mx = fmaxf(mx, v[k]);
        }
        float ssum = 0.0f;
#pragma unroll
        for (int k = 0; k < LSEG; k++) ssum += __expf(v[k]-mx);
        float a = mx + __logf(ssum);
        buf[3] = buf[2]; buf[2] = buf[1]; buf[1] = buf[0]; buf[0] = a;
        alph[m][b] = a;
    }
    int Lb = lengths[b];
    float nll = -alph[Lb-2][b];
    float tlen = (float)Lb;
#pragma unroll
    for (int off = 16; off; off >>= 1) {
        nll  += __shfl_down_sync(0xffffffffu, nll,  off);
        tlen += __shfl_down_sync(0xffffffffu, tlen, off);
    }
    if (b == 0) out[0] = nll / (tlen - 2.0f*BSZ);
}

// ---------------- launch ----------------
extern "C" void kernel_launch(void* const* d_in, const int* in_sizes, int n_in,
                              void* d_out, int out_size)
{
    const int*   x        = (const int*)  d_in[0];
    const int*   lengths  = (const int*)  d_in[1];
    const float* emb      = (const float*)d_in[2];
    const float* e2vb     = (const float*)d_in[3];
    const float* enc_Wih  = (const float*)d_in[4];
    const float* enc_Whh  = (const float*)d_in[5];
    const float* enc_bih  = (const float*)d_in[6];
    const float* enc_bhh  = (const float*)d_in[7];
    const float* enc_h0   = (const float*)d_in[8];
    const float* enc_c0   = (const float*)d_in[9];
    const float* dec_Wih  = (const float*)d_in[10];
    const float* dec_Whh  = (const float*)d_in[11];
    const float* dec_bih  = (const float*)d_in[12];
    const float* dec_bhh  = (const float*)d_in[13];
    const float* dht_W    = (const float*)d_in[14];
    const float* dht_b    = (const float*)d_in[15];
    const float* sos_W    = (const float*)d_in[16];
    const float* sos_b    = (const float*)d_in[17];
    float* out = (float*)d_out;

    float *p_inputs, *p_issing, *p_enc_xg, *p_enc_out, *p_sos, *p_dxg0, *p_vxg;
    float *p_gates, *p_dec_h, *p_dec_c, *p_dec_out, *p_pm, *p_ps, *p_lse, *p_tgt, *p_eos, *p_logpy;
    cudaGetSymbolAddress((void**)&p_inputs,  g_inputs);
    cudaGetSymbolAddress((void**)&p_issing,  g_issing);
    cudaGetSymbolAddress((void**)&p_enc_xg,  g_enc_xg);
    cudaGetSymbolAddress((void**)&p_enc_out, g_enc_out);
    cudaGetSymbolAddress((void**)&p_sos,     g_sos);
    cudaGetSymbolAddress((void**)&p_dxg0,    g_dxg0);
    cudaGetSymbolAddress((void**)&p_vxg,     g_vxg);
    cudaGetSymbolAddress((void**)&p_gates,   g_gates);
    cudaGetSymbolAddress((void**)&p_dec_h,   g_dec_h);
    cudaGetSymbolAddress((void**)&p_dec_c,   g_dec_c);
    cudaGetSymbolAddress((void**)&p_dec_out, g_dec_out);
    cudaGetSymbolAddress((void**)&p_pm,      g_pm);
    cudaGetSymbolAddress((void**)&p_ps,      g_ps);
    cudaGetSymbolAddress((void**)&p_lse,     g_lse);
    cudaGetSymbolAddress((void**)&p_tgt,     g_tgtlog);
    cudaGetSymbolAddress((void**)&p_eos,     g_eoslog);
    cudaGetSymbolAddress((void**)&p_logpy,   g_logpy);

    // 1. embed + is_single
    embed_kernel<<<MSZ*BSZ, 64>>>(x, emb, p_inputs, p_issing);
    // 2. encoder input gates
    gemm_tn<<<dim3(16, 64), 256>>>(p_inputs, enc_Wih, enc_bih, enc_bhh, p_enc_xg,
                                   MSZ*BSZ, G4, 0);
    // 3. encoder recurrence
    enc_lstm<<<BSZ, 256>>>(p_enc_xg, enc_Whh, enc_h0, enc_c0, p_enc_out);
    // 4. sos
    gemm_tn<<<dim3(4, 63), 256>>>(p_enc_out, sos_W, sos_b, nullptr, p_sos, SB, HSZ, 0);
    // 5. dec_h0 = tanh(...)
    gemm_tn<<<dim3(4, 63), 256>>>(p_enc_out, dht_W, dht_b, nullptr, p_dec_h, SB, HSZ, 1);
    // 6. vocab input gates
    gemm_tn<<<dim3(16, 63), 256>>>(emb, dec_Wih, dec_bih, dec_bhh, p_vxg, VSZ, G4, 0);
    // 7. step-0 input gates from sos
    gemm_tn<<<dim3(16, 63), 256>>>(p_sos, dec_Wih, dec_bih, dec_bhh, p_dxg0, SB, G4, 0);
    // 8. decoder: 5 sequential steps
    for (int t = 0; t <= LSEG; t++) {
        gemm_tn<<<dim3(16, 63), 256>>>(p_dec_h, dec_Whh, nullptr, nullptr, p_gates,
                                       SB, G4, 2);
        dec_point<<<SB, 256>>>(p_gates, p_dxg0, p_vxg, x, dec_bih, dec_bhh,
                               p_dec_h, p_dec_c, p_dec_out, t);
    }
    // 9. logits partials: 315 m-tiles x 4 vocab chunks = 1260 blocks
    logits_part<<<dim3(NROWS/64, VCH), 256>>>(p_dec_out, emb, e2vb, x,
                                              p_pm, p_ps, p_tgt, p_eos);
    // 10. merge partial LSEs
    lse_merge<<<(NROWS + 255)/256, 256>>>(p_pm, p_ps, p_lse);
    // 11. segment log-probs table
    logpy_kernel<<<((SSEG+1)*BSZ + 127)/128, 128>>>(p_lse, p_tgt, p_eos, p_issing, p_logpy);
    // 12. DP + reduction -> scalar
    dp_kernel<<<1, 32>>>(p_logpy, lengths, out);

    (void)in_sizes; (void)n_in; (void)out_size;
}

// round 11
// speedup vs baseline: 1.3075x; 1.2094x over previous
#include <cuda_runtime.h>
#include <cuda_bf16.h>
#include <math.h>
#include <stddef.h>
#include <stdint.h>

// ---------------- problem constants ----------------
#define VSZ   4000
#define ESZ   256
#define HSZ   256
#define MSZ   128
#define BSZ   32
#define LSEG  4
#define SSEG  126            // M-2
#define SB    (SSEG*BSZ)     // 4032
#define G4    (4*HSZ)        // 1024
#define NROWS ((LSEG+1)*SB)  // 20160
#define MTILES 158           // ceil(20160/128)
#define NROWS_PAD (MTILES*128)
#define VPAD  4096
#define NCHUNK 32
#define NEGINF (-1.0e6f)

// ---------------- scratch ----------------
__device__ float g_inputs [MSZ*BSZ*HSZ];
__device__ float g_issing [MSZ*BSZ];
__device__ float g_enc_xg [MSZ*BSZ*G4];
__device__ float g_enc_out[MSZ*BSZ*HSZ];
__device__ float g_sos    [SB*HSZ];
__device__ float g_dxg0   [SB*G4];
__device__ float g_vxg    [VSZ*G4];
__device__ float g_gates  [SB*G4];
__device__ float g_dec_h  [SB*HSZ];
__device__ float g_dec_c  [SB*HSZ];
__device__ __nv_bfloat16 g_abf[NROWS_PAD*ESZ];  // bf16 dec_out (pad rows stay 0)
__device__ __nv_bfloat16 g_bbf[VPAD*ESZ];       // bf16 embedding (pad rows 0)
__device__ float g_lse    [NROWS];
__device__ float g_tgtlog [NROWS];
__device__ float g_eoslog [NROWS];
__device__ float g_logpy  [(SSEG+1)*LSEG*BSZ];

__device__ __forceinline__ float sigmoidf(float x) { return 1.0f/(1.0f+__expf(-x)); }

// ================= mma.sync / ldmatrix / cp.async helpers (arch-neutral sm_80+) ===
__device__ __forceinline__ uint32_t smem_u32(const void* p) {
    return (uint32_t)__cvta_generic_to_shared(p);
}
__device__ __forceinline__ void cp16(uint32_t dst, const void* src) {
    asm volatile("cp.async.cg.shared.global [%0], [%1], 16;" :: "r"(dst), "l"(src));
}
#define CP_COMMIT() asm volatile("cp.async.commit_group;" ::: "memory")
#define CP_WAIT1()  asm volatile("cp.async.wait_group 1;"  ::: "memory")

__device__ __forceinline__ void ldsm4(uint32_t& r0, uint32_t& r1, uint32_t& r2,
                                      uint32_t& r3, uint32_t addr) {
    asm volatile("ldmatrix.sync.aligned.m8n8.x4.shared.b16 {%0,%1,%2,%3}, [%4];"
                 : "=r"(r0), "=r"(r1), "=r"(r2), "=r"(r3) : "r"(addr));
}
__device__ __forceinline__ void mma16816(float* d, uint32_t a0, uint32_t a1,
                                         uint32_t a2, uint32_t a3,
                                         uint32_t b0, uint32_t b1) {
    asm volatile("mma.sync.aligned.m16n8k16.row.col.f32.bf16.bf16.f32 "
        "{%0,%1,%2,%3}, {%4,%5,%6,%7}, {%8,%9}, {%0,%1,%2,%3};"
        : "+f"(d[0]), "+f"(d[1]), "+f"(d[2]), "+f"(d[3])
        : "r"(a0), "r"(a1), "r"(a2), "r"(a3), "r"(b0), "r"(b1));
}

// Load a 128-row x 256-col bf16 tile (512B rows) gmem->smem with XOR-swizzle.
// Swizzle: 16B chunk c of row r stored at chunk (c ^ (r & 7)).
__device__ __forceinline__ void load_tile_async(uint32_t smbase,
                                                const __nv_bfloat16* g, int tid) {
#pragma unroll
    for (int l = 0; l < 16; l++) {
        int u = tid + l*256;
        int row = u >> 5, c = u & 31;
        uint32_t dst = smbase + row*512 + ((c ^ (row & 7)) << 4);
        cp16(dst, (const char*)g + (size_t)row*512 + c*16);
    }
}

// ---------------- embed + is_single ----------------
__global__ void embed_kernel(const int* __restrict__ x, const float* __restrict__ emb,
                             float* __restrict__ inputs, float* __restrict__ issing)
{
    int row = blockIdx.x;
    int t = row >> 5, b = row & 31;
    int tok = x[b*MSZ + t];
    const float4* src = (const float4*)(emb + (size_t)tok*ESZ);
    float4* dst = (float4*)(inputs + (size_t)row*ESZ);
    dst[threadIdx.x] = src[threadIdx.x];
    if (threadIdx.x == 0)
        issing[row] = (tok == 0 || tok == 1 || tok == 2) ? NEGINF : 0.0f;
}

// ---------------- emb -> bf16 (padded) ----------------
__global__ void cvt_emb(const float* __restrict__ emb, __nv_bfloat16* __restrict__ bbf)
{
    int v = blockIdx.x, c = threadIdx.x;
    bbf[(size_t)v*ESZ + c] = (v < VSZ) ? __float2bfloat16(emb[(size_t)v*ESZ + c])
                                       : __float2bfloat16(0.0f);
}

// ---------------- generic C = A @ W^T (+b1+b2) [tanh] ; K=256 ----------------
__global__ __launch_bounds__(256)
void gemm_tn(const float* __restrict__ A, const float* __restrict__ W,
             const float* __restrict__ b1, const float* __restrict__ b2,
             float* __restrict__ C, int R, int N, int epi)
{
    const int K = 256;
    __shared__ float As[32][68];
    __shared__ float Ws[32][68];
    int tid = threadIdx.x;
    int tx = tid & 15, ty = tid >> 4;
    int m0 = blockIdx.y * 64, n0 = blockIdx.x * 64;

    float acc[4][4];
#pragma unroll
    for (int i = 0; i < 4; i++)
#pragma unroll
        for (int j = 0; j < 4; j++) acc[i][j] = 0.0f;

    for (int kc = 0; kc < K; kc += 32) {
#pragma unroll
        for (int l = 0; l < 2; l++) {
            int slot = tid + l*256;
            int row  = slot >> 3;
            int c4   = slot & 7;
            float4 av = make_float4(0,0,0,0), wv = make_float4(0,0,0,0);
            if (m0 + row < R) av = *(const float4*)(A + (size_t)(m0+row)*K + kc + c4*4);
            if (n0 + row < N) wv = *(const float4*)(W + (size_t)(n0+row)*K + kc + c4*4);
            As[c4*4+0][row] = av.x; As[c4*4+1][row] = av.y;
            As[c4*4+2][row] = av.z; As[c4*4+3][row] = av.w;
            Ws[c4*4+0][row] = wv.x; Ws[c4*4+1][row] = wv.y;
            Ws[c4*4+2][row] = wv.z; Ws[c4*4+3][row] = wv.w;
        }
        __syncthreads();
#pragma unroll
        for (int k = 0; k < 32; k++) {
            float4 a4 = *(const float4*)&As[k][ty*4];
            float4 b4 = *(const float4*)&Ws[k][tx*4];
            float ar[4] = {a4.x, a4.y, a4.z, a4.w};
            float br[4] = {b4.x, b4.y, b4.z, b4.w};
#pragma unroll
            for (int i = 0; i < 4; i++)
#pragma unroll
                for (int j = 0; j < 4; j++) acc[i][j] += ar[i]*br[j];
        }
        __syncthreads();
    }
#pragma unroll
    for (int i = 0; i < 4; i++) {
        int r = m0 + ty*4 + i;
        if (r >= R) continue;
#pragma unroll
        for (int j = 0; j < 4; j++) {
            int n = n0 + tx*4 + j;
            if (n >= N) continue;
            float v = acc[i][j];
            if (epi != 2) { v += b1[n]; if (b2) v += b2[n]; }
            if (epi == 1) v = tanhf(v);
            C[(size_t)r*N + n] = v;
        }
    }
}

// ---------------- encoder: one block per batch element ----------------
__global__ __launch_bounds__(256)
void enc_lstm(const float* __restrict__ xg, const float* __restrict__ Whh,
              const float* __restrict__ h0, const float* __restrict__ c0,
              float* __restrict__ enc_out)
{
    int b = blockIdx.x, tid = threadIdx.x;
    __shared__ float hsh[HSZ];
    hsh[tid] = h0[tid];
    float c = c0[tid];
    const float* w_i = Whh + (size_t)(tid      )*HSZ;
    const float* w_f = Whh + (size_t)(tid + 256)*HSZ;
    const float* w_g = Whh + (size_t)(tid + 512)*HSZ;
    const float* w_o = Whh + (size_t)(tid + 768)*HSZ;
    __syncthreads();

    for (int t = 0; t < MSZ; t++) {
        const float* xr = xg + ((size_t)t*BSZ + b)*G4;
        float gi = xr[tid], gf = xr[tid+256], gg = xr[tid+512], go = xr[tid+768];
#pragma unroll 4
        for (int k = 0; k < HSZ; k += 4) {
            float4 h4  = *(const float4*)&hsh[k];
            float4 wi4 = *(const float4*)(w_i + k);
            float4 wf4 = *(const float4*)(w_f + k);
            float4 wg4 = *(const float4*)(w_g + k);
            float4 wo4 = *(const float4*)(w_o + k);
            gi += h4.x*wi4.x + h4.y*wi4.y + h4.z*wi4.z + h4.w*wi4.w;
            gf += h4.x*wf4.x + h4.y*wf4.y + h4.z*wf4.z + h4.w*wf4.w;
            gg += h4.x*wg4.x + h4.y*wg4.y + h4.z*wg4.z + h4.w*wg4.w;
            go += h4.x*wo4.x + h4.y*wo4.y + h4.z*wo4.z + h4.w*wo4.w;
        }
        float cn = sigmoidf(gf)*c + sigmoidf(gi)*tanhf(gg);
        float hn = sigmoidf(go)*tanhf(cn);
        c = cn;
        __syncthreads();
        hsh[tid] = hn;
        enc_out[((size_t)t*BSZ + b)*HSZ + tid] = 0.5f*hn;
        __syncthreads();
    }
}

// ---------------- decoder pointwise (writes bf16 dec_out) ----------------
__global__ void dec_point(const float* __restrict__ gates, const float* __restrict__ xg0,
                          const float* __restrict__ vxg, const int* __restrict__ x,
                          const float* __restrict__ bih, const float* __restrict__ bhh,
                          float* __restrict__ h, float* __restrict__ cc,
                          __nv_bfloat16* __restrict__ abf, int t)
{
    int r = blockIdx.x, j = threadIdx.x;
    int s = r >> 5, b = r & 31;
    const float* base = nullptr;
    if (t == 0) base = xg0 + (size_t)r*G4;
    else {
        int pos = s + t;
        if (pos <= MSZ-1) base = vxg + (size_t)x[b*MSZ + pos]*G4;
    }
    float xi, xf, xgv, xo;
    if (base) { xi = base[j]; xf = base[j+256]; xgv = base[j+512]; xo = base[j+768]; }
    else {     xi = bih[j]+bhh[j]; xf = bih[j+256]+bhh[j+256];
               xgv = bih[j+512]+bhh[j+512]; xo = bih[j+768]+bhh[j+768]; }
    const float* gr = gates + (size_t)r*G4;
    float gi = gr[j] + xi, gf = gr[j+256] + xf, gg = gr[j+512] + xgv, go = gr[j+768] + xo;
    float cp = (t == 0) ? 0.0f : cc[(size_t)r*HSZ + j];
    float cn = sigmoidf(gf)*cp + sigmoidf(gi)*tanhf(gg);
    float hn = sigmoidf(go)*tanhf(cn);
    cc[(size_t)r*HSZ + j] = cn;
    h [(size_t)r*HSZ + j] = hn;
    abf[((size_t)t*SB + r)*ESZ + j] = __float2bfloat16(hn);
}

// ================ bf16 mma.sync logits + fused online LSE ================
// One block per 128-row M-tile; 8 warps in 4(row-band) x 2(col-half) grid.
// Each warp: 32x64 patch = 2 m16-tiles x 8 n8-tiles, K=256 in 16 k16 steps.
// SMEM: A(64K) | B0(64K) | B1(64K) | bias(16K) | red(1K)
#define SMA    0
#define SMB0   65536
#define SMB1   131072
#define SMBIAS 196608
#define SMRED  212992
#define SMTOT  214016

__global__ __launch_bounds__(256, 1)
void logits_mma(const __nv_bfloat16* __restrict__ abf, const __nv_bfloat16* __restrict__ bbf,
                const float* __restrict__ e2vb, const int* __restrict__ x,
                float* __restrict__ lse, float* __restrict__ tgtlog,
                float* __restrict__ eoslog)
{
    extern __shared__ char sm[];
    uint32_t smb = smem_u32(sm);
    int tid = threadIdx.x, wid = tid >> 5, lane = tid & 31;
    int band = wid & 3, half = wid >> 2;
    int m0 = blockIdx.x * 128;

    // prologue: A tile + B0 (group 0), B1 (group 1), bias (plain)
    load_tile_async(smb + SMA, abf + (size_t)m0*ESZ, tid);
    CP_COMMIT();
    load_tile_async(smb + SMB0, bbf, tid);
    CP_COMMIT();
    load_tile_async(smb + SMB1, bbf + (size_t)128*ESZ, tid);
    CP_COMMIT();
    float* bias_s = (float*)(sm + SMBIAS);
#pragma unroll
    for (int l = 0; l < 16; l++) {
        int i = tid + l*256;
        bias_s[i] = (i < VSZ) ? e2vb[i] : 0.0f;
    }

    // per-thread row slots: sl = mi*2+hi -> local row band*32 + mi*16 + hi*8 + lane/4
    int vt[4];
    float Mv[4], Sv[4];
#pragma unroll
    for (int sl = 0; sl < 4; sl++) {
        int rl = band*32 + (sl >> 1)*16 + (sl & 1)*8 + (lane >> 2);
        int row = m0 + rl;
        vt[sl] = -1;
        if (row < NROWS) {
            int t = row / SB; int rr = row % SB; int s = rr >> 5; int b = rr & 31;
            if (t < LSEG) { int pos = s + 1 + t; vt[sl] = (pos <= MSZ-1) ? x[b*MSZ + pos] : 0; }
        }
        Mv[sl] = -3.0e38f; Sv[sl] = 0.0f;
    }

    // ldmatrix lane addressing (row&7 == lane&7 for all our tiles)
    int swz = lane & 7;
    uint32_t aBase[2];
#pragma unroll
    for (int mi = 0; mi < 2; mi++)
        aBase[mi] = smb + SMA + (uint32_t)(band*32 + mi*16 + (lane & 15))*512;
    int hiA = lane >> 4;                 // A: chunk offset bit
    int hiB = (lane >> 3) & 1;           // B: chunk offset bit
    uint32_t bRow[4];
#pragma unroll
    for (int p = 0; p < 4; p++)
        bRow[p] = (uint32_t)(half*64 + p*16 + ((lane >> 4) & 1)*8 + (lane & 7))*512;

    CP_WAIT1();          // A + B0 complete (B1 may be in flight)
    __syncthreads();

    for (int c = 0; c < NCHUNK; c++) {
        uint32_t bbase = smb + ((c & 1) ? SMB1 : SMB0);
        float acc[2][8][4];
#pragma unroll
        for (int mi = 0; mi < 2; mi++)
#pragma unroll
            for (int ni = 0; ni < 8; ni++)
#pragma unroll
                for (int k = 0; k < 4; k++) acc[mi][ni][k] = 0.0f;

#pragma unroll
        for (int kb = 0; kb < 16; kb++) {
            uint32_t a[2][4];
#pragma unroll
            for (int mi = 0; mi < 2; mi++) {
                uint32_t addr = aBase[mi] + (uint32_t)(((2*kb + hiA) ^ swz) << 4);
                ldsm4(a[mi][0], a[mi][1], a[mi][2], a[mi][3], addr);
            }
#pragma unroll
            for (int p = 0; p < 4; p++) {
                uint32_t b0, b1, b2, b3;
                uint32_t addr = bbase + bRow[p] + (uint32_t)(((2*kb + hiB) ^ swz) << 4);
                ldsm4(b0, b1, b2, b3, addr);
#pragma unroll
                for (int mi = 0; mi < 2; mi++) {
                    mma16816(acc[mi][2*p    ], a[mi][0], a[mi][1], a[mi][2], a[mi][3], b0, b1);
                    mma16816(acc[mi][2*p + 1], a[mi][0], a[mi][1], a[mi][2], a[mi][3], b2, b3);
                }
            }
        }

        // epilogue: fold chunk into per-row online LSE + target/EOS extraction
        int vb = c*128 + half*64 + (lane & 3)*2;
#pragma unroll
        for (int sl = 0; sl < 4; sl++) {
            int mi = sl >> 1, hi = sl & 1;
            int rowg = m0 + band*32 + mi*16 + hi*8 + (lane >> 2);
            float gm = -3.0e38f;
            float lv[16];
#pragma unroll
            for (int ni = 0; ni < 8; ni++) {
#pragma unroll
                for (int j = 0; j < 2; j++) {
                    int v = vb + ni*8 + j;
                    float val = acc[mi][ni][hi*2 + j] + bias_s[v];
                    if (v == vt[sl]) tgtlog[rowg] = val;
                    if (v == 3 && rowg < NROWS) eoslog[rowg] = val;
                    float e = (v < VSZ) ? val : -1.0e30f;
                    lv[ni*2 + j] = e;
                    gm = fmaxf(gm, e);
                }
            }
            float gs = 0.0f;
#pragma unroll
            for (int q = 0; q < 16; q++) gs += __expf(lv[q] - gm);
            // quad reduce (lanes sharing this row: xor 1, 2)
#pragma unroll
            for (int d = 1; d <= 2; d <<= 1) {
                float m2 = __shfl_xor_sync(0xffffffffu, gm, d);
                float s2 = __shfl_xor_sync(0xffffffffu, gs, d);
                float nm = fmaxf(gm, m2);
                gs = gs*__expf(gm - nm) + s2*__expf(m2 - nm);
                gm = nm;
            }
            // merge into running
            float nm = fmaxf(Mv[sl], gm);
            Sv[sl] = Sv[sl]*__expf(Mv[sl] - nm) + gs*__expf(gm - nm);
            Mv[sl] = nm;
        }

        __syncthreads();     // everyone done reading buf[c&1]
        if (c + 2 < NCHUNK)
            load_tile_async(smb + ((c & 1) ? SMB1 : SMB0),
                            bbf + (size_t)(c + 2)*128*ESZ, tid);
        CP_COMMIT();
        CP_WAIT1();          // B[c+1] complete
        __syncthreads();
    }

    // cross-half merge via smem
    float* smm = (float*)(sm + SMRED);
    float* sms = smm + 128;
    if (half == 0 && (lane & 3) == 0) {
#pragma unroll
        for (int sl = 0; sl < 4; sl++) {
            int rl = band*32 + (sl >> 1)*16 + (sl & 1)*8 + (lane >> 2);
            smm[rl] = Mv[sl]; sms[rl] = Sv[sl];
        }
    }
    __syncthreads();
    if (half == 1 && (lane & 3) == 0) {
#pragma unroll
        for (int sl = 0; sl < 4; sl++) {
            int rl = band*32 + (sl >> 1)*16 + (sl & 1)*8 + (lane >> 2);
            float m2 = smm[rl], s2 = sms[rl];
            float nm = fmaxf(Mv[sl], m2);
            float s = Sv[sl]*__expf(Mv[sl] - nm) + s2*__expf(m2 - nm);
            int rowg = m0 + rl;
            if (rowg < NROWS) lse[rowg] = nm + __logf(s);
        }
    }
}

// ---------------- segment log-probs -> logpy table ----------------
__global__ void logpy_kernel(const float* __restrict__ lse, const float* __restrict__ tgtlog,
                             const float* __restrict__ eoslog, const float* __restrict__ issing,
                             float* __restrict__ logpy)
{
    int idx = blockIdx.x*blockDim.x + threadIdx.x;
    if (idx >= (SSEG+1)*BSZ) return;
    int e = idx >> 5, b = idx & 31;
    if (e == 0) {
        logpy[b] = 0.0f;
        for (int k = 1; k < LSEG; k++) logpy[k*BSZ + b] = NEGINF;
        return;
    }
    int s = e - 1;
    int r = s*BSZ + b;
    float cum = 0.0f;
    float is_start = issing[(s+1)*BSZ + b];
    int jlen = SSEG - s; if (jlen > LSEG) jlen = LSEG;
    for (int k = 0; k < LSEG; k++) {
        int rowk = k*SB + r;
        float tlp = tgtlog[rowk] - lse[rowk];
        float segis = ((s+1+k) <= MSZ-1) ? issing[(s+1+k)*BSZ + b] : 0.0f;
        cum += tlp + ((k >= 1) ? segis : 0.0f);
        int rowe = (k+1)*SB + r;
        float eos = eoslog[rowe] - lse[rowe];
        float val = cum + ((k >= 1) ? is_start : 0.0f) + eos;
        if (k >= jlen) val = NEGINF;
        logpy[(e*LSEG + k)*BSZ + b] = val;
    }
}

// ---------------- final DP over segmentations ----------------
__global__ void dp_kernel(const float* __restrict__ logpy, const int* __restrict__ lengths,
                          float* __restrict__ out)
{
    int b = threadIdx.x;
    __shared__ float alph[MSZ-1][BSZ];
    float buf[LSEG] = {0.0f, NEGINF, NEGINF, NEGINF};
    alph[0][b] = 0.0f;
    for (int m = 1; m < MSZ-1; m++) {
        float v[LSEG], mx = -3.0e38f;
#pragma unroll
        for (int k = 0; k < LSEG; k++) {
            int e = m - k;
            float slp = (e >= 1) ? logpy[(e*LSEG + k)*BSZ + b] : NEGINF;
            v[k] = buf[k] + slp;
            mx = fmaxf(mx, v[k]);
        }
        float ssum = 0.0f;
#pragma unroll
        for (int k = 0; k < LSEG; k++) ssum += __expf(v[k]-mx);
        float a = mx + __logf(ssum);
        buf[3] = buf[2]; buf[2] = buf[1]; buf[1] = buf[0]; buf[0] = a;
        alph[m][b] = a;
    }
    int Lb = lengths[b];
    float nll = -alph[Lb-2][b];
    float tlen = (float)Lb;
#pragma unroll
    for (int off = 16; off; off >>= 1) {
        nll  += __shfl_down_sync(0xffffffffu, nll,  off);
        tlen += __shfl_down_sync(0xffffffffu, tlen, off);
    }
    if (b == 0) out[0] = nll / (tlen - 2.0f*BSZ);
}

// ---------------- launch ----------------
extern "C" void kernel_launch(void* const* d_in, const int* in_sizes, int n_in,
                              void* d_out, int out_size)
{
    const int*   x        = (const int*)  d_in[0];
    const int*   lengths  = (const int*)  d_in[1];
    const float* emb      = (const float*)d_in[2];
    const float* e2vb     = (const float*)d_in[3];
    const float* enc_Wih  = (const float*)d_in[4];
    const float* enc_Whh  = (const float*)d_in[5];
    const float* enc_bih  = (const float*)d_in[6];
    const float* enc_bhh  = (const float*)d_in[7];
    const float* enc_h0   = (const float*)d_in[8];
    const float* enc_c0   = (const float*)d_in[9];
    const float* dec_Wih  = (const float*)d_in[10];
    const float* dec_Whh  = (const float*)d_in[11];
    const float* dec_bih  = (const float*)d_in[12];
    const float* dec_bhh  = (const float*)d_in[13];
    const float* dht_W    = (const float*)d_in[14];
    const float* dht_b    = (const float*)d_in[15];
    const float* sos_W    = (const float*)d_in[16];
    const float* sos_b    = (const float*)d_in[17];
    float* out = (float*)d_out;

    float *p_inputs, *p_issing, *p_enc_xg, *p_enc_out, *p_sos, *p_dxg0, *p_vxg;
    float *p_gates, *p_dec_h, *p_dec_c, *p_lse, *p_tgt, *p_eos, *p_logpy;
    __nv_bfloat16 *p_abf, *p_bbf;
    cudaGetSymbolAddress((void**)&p_inputs,  g_inputs);
    cudaGetSymbolAddress((void**)&p_issing,  g_issing);
    cudaGetSymbolAddress((void**)&p_enc_xg,  g_enc_xg);
    cudaGetSymbolAddress((void**)&p_enc_out, g_enc_out);
    cudaGetSymbolAddress((void**)&p_sos,     g_sos);
    cudaGetSymbolAddress((void**)&p_dxg0,    g_dxg0);
    cudaGetSymbolAddress((void**)&p_vxg,     g_vxg);
    cudaGetSymbolAddress((void**)&p_gates,   g_gates);
    cudaGetSymbolAddress((void**)&p_dec_h,   g_dec_h);
    cudaGetSymbolAddress((void**)&p_dec_c,   g_dec_c);
    cudaGetSymbolAddress((void**)&p_abf,     g_abf);
    cudaGetSymbolAddress((void**)&p_bbf,     g_bbf);
    cudaGetSymbolAddress((void**)&p_lse,     g_lse);
    cudaGetSymbolAddress((void**)&p_tgt,     g_tgtlog);
    cudaGetSymbolAddress((void**)&p_eos,     g_eoslog);
    cudaGetSymbolAddress((void**)&p_logpy,   g_logpy);

    cudaFuncSetAttribute(logits_mma, cudaFuncAttributeMaxDynamicSharedMemorySize, SMTOT);

    // 1. embed + is_single ; emb -> bf16
    embed_kernel<<<MSZ*BSZ, 64>>>(x, emb, p_inputs, p_issing);
    cvt_emb<<<VPAD, 256>>>(emb, p_bbf);
    // 2. encoder input gates
    gemm_tn<<<dim3(16, 64), 256>>>(p_inputs, enc_Wih, enc_bih, enc_bhh, p_enc_xg,
                                   MSZ*BSZ, G4, 0);
    // 3. encoder recurrence
    enc_lstm<<<BSZ, 256>>>(p_enc_xg, enc_Whh, enc_h0, enc_c0, p_enc_out);
    // 4. sos
    gemm_tn<<<dim3(4, 63), 256>>>(p_enc_out, sos_W, sos_b, nullptr, p_sos, SB, HSZ, 0);
    // 5. dec_h0 = tanh(...)
    gemm_tn<<<dim3(4, 63), 256>>>(p_enc_out, dht_W, dht_b, nullptr, p_dec_h, SB, HSZ, 1);
    // 6. vocab input gates
    gemm_tn<<<dim3(16, 63), 256>>>(emb, dec_Wih, dec_bih, dec_bhh, p_vxg, VSZ, G4, 0);
    // 7. step-0 input gates from sos
    gemm_tn<<<dim3(16, 63), 256>>>(p_sos, dec_Wih, dec_bih, dec_bhh, p_dxg0, SB, G4, 0);
    // 8. decoder: 5 sequential steps (writes bf16 dec_out)
    for (int t = 0; t <= LSEG; t++) {
        gemm_tn<<<dim3(16, 63), 256>>>(p_dec_h, dec_Whh, nullptr, nullptr, p_gates,
                                       SB, G4, 2);
        dec_point<<<SB, 256>>>(p_gates, p_dxg0, p_vxg, x, dec_bih, dec_bhh,
                               p_dec_h, p_dec_c, p_abf, t);
    }
    // 9. bf16 mma.sync logits + fused LSE/target/EOS
    logits_mma<<<MTILES, 256, SMTOT>>>(p_abf, p_bbf, e2vb, x, p_lse, p_tgt, p_eos);
    // 10. segment log-probs table
    logpy_kernel<<<((SSEG+1)*BSZ + 127)/128, 128>>>(p_lse, p_tgt, p_eos, p_issing, p_logpy);
    // 11. DP + reduction -> scalar
    dp_kernel<<<1, 32>>>(p_logpy, lengths, out);

    (void)in_sizes; (void)n_in; (void)out_size;
}

// round 14
// speedup vs baseline: 2.5258x; 1.9318x over previous
#include <cuda_runtime.h>
#include <cuda_bf16.h>
#include <math.h>
#include <stddef.h>
#include <stdint.h>

// ---------------- problem constants ----------------
#define VSZ   4000
#define ESZ   256
#define HSZ   256
#define MSZ   128
#define BSZ   32
#define LSEG  4
#define SSEG  126            // M-2
#define SB    (SSEG*BSZ)     // 4032
#define G4    (4*HSZ)        // 1024
#define NROWS ((LSEG+1)*SB)  // 20160
#define MTILES 158           // ceil(20160/128)
#define NROWS_PAD (MTILES*128)
#define VPAD  4096
#define NCHUNK 32
#define NEGINF (-1.0e6f)

// ---------------- scratch ----------------
__device__ float g_issing [MSZ*BSZ];
__device__ float g_enc_xg [MSZ*BSZ*G4];
__device__ float g_sos    [4096*HSZ];    // fp32 out (padded rows)
__device__ float g_dxg0   [4096*G4];
__device__ float g_vxg    [VPAD*G4];
__device__ float g_gates  [4096*G4];
__device__ float g_dec_h  [4096*HSZ];    // fp32 out for dht gemm
__device__ float g_dec_c  [SB*HSZ];
__device__ __nv_bfloat16 g_ibf  [MSZ*BSZ*ESZ];   // bf16 embedded inputs
__device__ __nv_bfloat16 g_eobf [MSZ*BSZ*ESZ];   // bf16 0.5*enc_out
__device__ __nv_bfloat16 g_sosbf[4096*ESZ];
__device__ __nv_bfloat16 g_dhbf [4096*ESZ];      // bf16 decoder h
__device__ __nv_bfloat16 g_abf[NROWS_PAD*ESZ];   // bf16 dec_out
__device__ __nv_bfloat16 g_bbf[VPAD*ESZ];        // bf16 embedding (pad rows 0)
__device__ __nv_bfloat16 g_wihe[G4*ESZ];
__device__ __nv_bfloat16 g_whhe[G4*ESZ];
__device__ __nv_bfloat16 g_wihd[G4*ESZ];
__device__ __nv_bfloat16 g_whhd[G4*ESZ];
__device__ __nv_bfloat16 g_sosw[HSZ*ESZ];
__device__ __nv_bfloat16 g_dhtw[HSZ*ESZ];
__device__ float g_lse    [NROWS];
__device__ float g_tgtlog [NROWS];
__device__ float g_eoslog [NROWS];
__device__ float g_logpy  [(SSEG+1)*LSEG*BSZ];

__device__ __forceinline__ float sigmoidf(float x) { return 1.0f/(1.0f+__expf(-x)); }

// ================= mma.sync / ldmatrix / cp.async helpers ===
__device__ __forceinline__ uint32_t smem_u32(const void* p) {
    return (uint32_t)__cvta_generic_to_shared(p);
}
__device__ __forceinline__ void cp16(uint32_t dst, const void* src) {
    asm volatile("cp.async.cg.shared.global [%0], [%1], 16;" :: "r"(dst), "l"(src));
}
#define CP_COMMIT() asm volatile("cp.async.commit_group;" ::: "memory")
#define CP_WAIT1()  asm volatile("cp.async.wait_group 1;"  ::: "memory")
#define CP_WAIT0()  asm volatile("cp.async.wait_group 0;"  ::: "memory")

__device__ __forceinline__ void ldsm4(uint32_t& r0, uint32_t& r1, uint32_t& r2,
                                      uint32_t& r3, uint32_t addr) {
    asm volatile("ldmatrix.sync.aligned.m8n8.x4.shared.b16 {%0,%1,%2,%3}, [%4];"
                 : "=r"(r0), "=r"(r1), "=r"(r2), "=r"(r3) : "r"(addr));
}
__device__ __forceinline__ void mma16816(float* d, uint32_t a0, uint32_t a1,
                                         uint32_t a2, uint32_t a3,
                                         uint32_t b0, uint32_t b1) {
    asm volatile("mma.sync.aligned.m16n8k16.row.col.f32.bf16.bf16.f32 "
        "{%0,%1,%2,%3}, {%4,%5,%6,%7}, {%8,%9}, {%0,%1,%2,%3};"
        : "+f"(d[0]), "+f"(d[1]), "+f"(d[2]), "+f"(d[3])
        : "r"(a0), "r"(a1), "r"(a2), "r"(a3), "r"(b0), "r"(b1));
}

// Load a 128-row x 256-col bf16 tile (512B rows) gmem->smem with XOR-swizzle.
__device__ __forceinline__ void load_tile_async(uint32_t smbase,
                                                const __nv_bfloat16* g, int tid) {
#pragma unroll
    for (int l = 0; l < 16; l++) {
        int u = tid + l*256;
        int row = u >> 5, c = u & 31;
        uint32_t dst = smbase + row*512 + ((c ^ (row & 7)) << 4);
        cp16(dst, (const char*)g + (size_t)row*512 + c*16);
    }
}

// ---------------- embed (bf16) + is_single ----------------
__global__ void embed_kernel(const int* __restrict__ x, const float* __restrict__ emb,
                             __nv_bfloat16* __restrict__ ibf, float* __restrict__ issing)
{
    int row = blockIdx.x;
    int t = row >> 5, b = row & 31;
    int tok = x[b*MSZ + t];
    float4 v = ((const float4*)(emb + (size_t)tok*ESZ))[threadIdx.x];
    __nv_bfloat16* d = ibf + (size_t)row*ESZ + threadIdx.x*4;
    d[0] = __float2bfloat16(v.x); d[1] = __float2bfloat16(v.y);
    d[2] = __float2bfloat16(v.z); d[3] = __float2bfloat16(v.w);
    if (threadIdx.x == 0)
        issing[row] = (tok == 0 || tok == 1 || tok == 2) ? NEGINF : 0.0f;
}

// ---------------- emb -> bf16 (padded) ----------------
__global__ void cvt_emb(const float* __restrict__ emb, __nv_bfloat16* __restrict__ bbf)
{
    int v = blockIdx.x, c = threadIdx.x;
    bbf[(size_t)v*ESZ + c] = (v < VSZ) ? __float2bfloat16(emb[(size_t)v*ESZ + c])
                                       : __float2bfloat16(0.0f);
}

// ---------------- generic fp32 -> bf16 ----------------
__global__ void cvt_bf(const float* __restrict__ s, __nv_bfloat16* __restrict__ d, int n)
{
    int i = blockIdx.x*256 + threadIdx.x;
    if (i < n) d[i] = __float2bfloat16(s[i]);
}

// ================ generic bf16 tensor-core GEMM: C = A @ W^T (+bias)[tanh] ===
// A[R_pad,256] bf16, W[N,256] bf16. Block = 128 rows x 128 cols. K=256.
// epi: 0=+bias, 1=tanh(+bias), 2=raw. Cbf optional bf16 duplicate output.
#define GM_SMA 0
#define GM_SMW 65536
#define GM_TOT 131072

__global__ __launch_bounds__(256, 1)
void gemm_mma(const __nv_bfloat16* __restrict__ A, const __nv_bfloat16* __restrict__ W,
              const float* __restrict__ b1, const float* __restrict__ b2,
              float* __restrict__ C, __nv_bfloat16* __restrict__ Cbf,
              int R, int N, int epi)
{
    extern __shared__ char sm[];
    uint32_t smb = smem_u32(sm);
    int tid = threadIdx.x, wid = tid >> 5, lane = tid & 31;
    int band = wid & 3, half = wid >> 2;
    int m0 = blockIdx.x * 128, n0 = blockIdx.y * 128;

    load_tile_async(smb + GM_SMA, A + (size_t)m0*ESZ, tid);
    load_tile_async(smb + GM_SMW, W + (size_t)n0*ESZ, tid);
    CP_COMMIT();

    int swz = lane & 7;
    uint32_t aBase[2];
#pragma unroll
    for (int mi = 0; mi < 2; mi++)
        aBase[mi] = smb + GM_SMA + (uint32_t)(band*32 + mi*16 + (lane & 15))*512;
    int hiA = lane >> 4;
    int hiB = (lane >> 3) & 1;
    uint32_t bRow[4];
#pragma unroll
    for (int p = 0; p < 4; p++)
        bRow[p] = smb + GM_SMW + (uint32_t)(half*64 + p*16 + ((lane >> 4) & 1)*8 + (lane & 7))*512;

    float acc[2][8][4];
#pragma unroll
    for (int mi = 0; mi < 2; mi++)
#pragma unroll
        for (int ni = 0; ni < 8; ni++)
#pragma unroll
            for (int k = 0; k < 4; k++) acc[mi][ni][k] = 0.0f;

    CP_WAIT0();
    __syncthreads();

#pragma unroll
    for (int kb = 0; kb < 16; kb++) {
        uint32_t a[2][4];
#pragma unroll
        for (int mi = 0; mi < 2; mi++) {
            uint32_t addr = aBase[mi] + (uint32_t)(((2*kb + hiA) ^ swz) << 4);
            ldsm4(a[mi][0], a[mi][1], a[mi][2], a[mi][3], addr);
        }
#pragma unroll
        for (int p = 0; p < 4; p++) {
            uint32_t b0, b1r, b2r, b3;
            uint32_t addr = bRow[p] + (uint32_t)(((2*kb + hiB) ^ swz) << 4);
            ldsm4(b0, b1r, b2r, b3, addr);
#pragma unroll
            for (int mi = 0; mi < 2; mi++) {
                mma16816(acc[mi][2*p    ], a[mi][0], a[mi][1], a[mi][2], a[mi][3], b0, b1r);
                mma16816(acc[mi][2*p + 1], a[mi][0], a[mi][1], a[mi][2], a[mi][3], b2r, b3);
            }
        }
    }

    // epilogue
#pragma unroll
    for (int mi = 0; mi < 2; mi++) {
#pragma unroll
        for (int hi = 0; hi < 2; hi++) {
            int row = m0 + band*32 + mi*16 + hi*8 + (lane >> 2);
            if (row >= R) continue;
#pragma unroll
            for (int ni = 0; ni < 8; ni++) {
#pragma unroll
                for (int j = 0; j < 2; j++) {
                    int col = n0 + half*64 + ni*8 + (lane & 3)*2 + j;
                    float v = acc[mi][ni][hi*2 + j];
                    if (epi != 2) { v += b1[col]; if (b2) v += b2[col]; }
                    if (epi == 1) v = tanhf(v);
                    C[(size_t)row*N + col] = v;
                    if (Cbf) Cbf[(size_t)row*N + col] = __float2bfloat16(v);
                }
            }
        }
    }
}

// ---------------- encoder: bf16 weights, one block per batch element ----------------
__device__ __forceinline__ void fma2bf(float& acc, uint32_t u, float hlo, float hhi) {
    acc = fmaf(__uint_as_float(u << 16), hlo, acc);
    acc = fmaf(__uint_as_float(u & 0xffff0000u), hhi, acc);
}

__global__ __launch_bounds__(256)
void enc_lstm(const float* __restrict__ xg, const __nv_bfloat16* __restrict__ whhbf,
              const float* __restrict__ h0, const float* __restrict__ c0,
              __nv_bfloat16* __restrict__ eobf)
{
    int b = blockIdx.x, tid = threadIdx.x;
    __shared__ float hsh[HSZ];
    hsh[tid] = h0[tid];
    float c = c0[tid];
    const uint4* w_i = (const uint4*)(whhbf + (size_t)(tid      )*HSZ);
    const uint4* w_f = (const uint4*)(whhbf + (size_t)(tid + 256)*HSZ);
    const uint4* w_g = (const uint4*)(whhbf + (size_t)(tid + 512)*HSZ);
    const uint4* w_o = (const uint4*)(whhbf + (size_t)(tid + 768)*HSZ);
    __syncthreads();

    for (int t = 0; t < MSZ; t++) {
        const float* xr = xg + ((size_t)t*BSZ + b)*G4;
        float gi = xr[tid], gf = xr[tid+256], gg = xr[tid+512], go = xr[tid+768];
#pragma unroll 4
        for (int cc8 = 0; cc8 < 32; cc8++) {      // 8 k-values per iter
            uint4 qi = w_i[cc8], qf = w_f[cc8], qg = w_g[cc8], qo = w_o[cc8];
            float4 ha = *(const float4*)&hsh[cc8*8];
            float4 hb = *(const float4*)&hsh[cc8*8 + 4];
            fma2bf(gi, qi.x, ha.x, ha.y); fma2bf(gi, qi.y, ha.z, ha.w);
            fma2bf(gi, qi.z, hb.x, hb.y); fma2bf(gi, qi.w, hb.z, hb.w);
            fma2bf(gf, qf.x, ha.x, ha.y); fma2bf(gf, qf.y, ha.z, ha.w);
            fma2bf(gf, qf.z, hb.x, hb.y); fma2bf(gf, qf.w, hb.z, hb.w);
            fma2bf(gg, qg.x, ha.x, ha.y); fma2bf(gg, qg.y, ha.z, ha.w);
            fma2bf(gg, qg.z, hb.x, hb.y); fma2bf(gg, qg.w, hb.z, hb.w);
            fma2bf(go, qo.x, ha.x, ha.y); fma2bf(go, qo.y, ha.z, ha.w);
            fma2bf(go, qo.z, hb.x, hb.y); fma2bf(go, qo.w, hb.z, hb.w);
        }
        float cn = sigmoidf(gf)*c + sigmoidf(gi)*tanhf(gg);
        float hn = sigmoidf(go)*tanhf(cn);
        c = cn;
        __syncthreads();
        hsh[tid] = hn;
        eobf[((size_t)t*BSZ + b)*HSZ + tid] = __float2bfloat16(0.5f*hn);
        __syncthreads();
    }
}

// ---------------- decoder pointwise (writes bf16 h + dec_out) ----------------
__global__ void dec_point(const float* __restrict__ gates, const float* __restrict__ xg0,
                          const float* __restrict__ vxg, const int* __restrict__ x,
                          const float* __restrict__ bih, const float* __restrict__ bhh,
                          float* __restrict__ cc, __nv_bfloat16* __restrict__ hbf,
                          __nv_bfloat16* __restrict__ abf, int t)
{
    int r = blockIdx.x, j = threadIdx.x;
    int s = r >> 5, b = r & 31;
    const float* base = nullptr;
    if (t == 0) base = xg0 + (size_t)r*G4;
    else {
        int pos = s + t;
        if (pos <= MSZ-1) base = vxg + (size_t)x[b*MSZ + pos]*G4;
    }
    float xi, xf, xgv, xo;
    if (base) { xi = base[j]; xf = base[j+256]; xgv = base[j+512]; xo = base[j+768]; }
    else {     xi = bih[j]+bhh[j]; xf = bih[j+256]+bhh[j+256];
               xgv = bih[j+512]+bhh[j+512]; xo = bih[j+768]+bhh[j+768]; }
    const float* gr = gates + (size_t)r*G4;
    float gi = gr[j] + xi, gf = gr[j+256] + xf, gg = gr[j+512] + xgv, go = gr[j+768] + xo;
    float cp = (t == 0) ? 0.0f : cc[(size_t)r*HSZ + j];
    float cn = sigmoidf(gf)*cp + sigmoidf(gi)*tanhf(gg);
    float hn = sigmoidf(go)*tanhf(cn);
    cc[(size_t)r*HSZ + j] = cn;
    __nv_bfloat16 hb = __float2bfloat16(hn);
    hbf[(size_t)r*HSZ + j] = hb;
    abf[((size_t)t*SB + r)*ESZ + j] = hb;
}

// ================ bf16 mma.sync logits + fused online LSE ===
#define SMA    0
#define SMB0   65536
#define SMB1   131072
#define SMBIAS 196608
#define SMRED  212992
#define SMTOT  214016

__global__ __launch_bounds__(256, 1)
void logits_mma(const __nv_bfloat16* __restrict__ abf, const __nv_bfloat16* __restrict__ bbf,
                const float* __restrict__ e2vb, const int* __restrict__ x,
                float* __restrict__ lse, float* __restrict__ tgtlog,
                float* __restrict__ eoslog)
{
    extern __shared__ char sm[];
    uint32_t smb = smem_u32(sm);
    int tid = threadIdx.x, wid = tid >> 5, lane = tid & 31;
    int band = wid & 3, half = wid >> 2;
    int m0 = blockIdx.x * 128;

    load_tile_async(smb + SMA, abf + (size_t)m0*ESZ, tid);
    CP_COMMIT();
    load_tile_async(smb + SMB0, bbf, tid);
    CP_COMMIT();
    load_tile_async(smb + SMB1, bbf + (size_t)128*ESZ, tid);
    CP_COMMIT();
    float* bias_s = (float*)(sm + SMBIAS);
#pragma unroll
    for (int l = 0; l < 16; l++) {
        int i = tid + l*256;
        bias_s[i] = (i < VSZ) ? e2vb[i] : 0.0f;
    }

    int vt[4];
    float Mv[4], Sv[4];
#pragma unroll
    for (int sl = 0; sl < 4; sl++) {
        int rl = band*32 + (sl >> 1)*16 + (sl & 1)*8 + (lane >> 2);
        int row = m0 + rl;
        vt[sl] = -1;
        if (row < NROWS) {
            int t = row / SB; int rr = row % SB; int s = rr >> 5; int b = rr & 31;
            if (t < LSEG) { int pos = s + 1 + t; vt[sl] = (pos <= MSZ-1) ? x[b*MSZ + pos] : 0; }
        }
        Mv[sl] = -3.0e38f; Sv[sl] = 0.0f;
    }

    int swz = lane & 7;
    uint32_t aBase[2];
#pragma unroll
    for (int mi = 0; mi < 2; mi++)
        aBase[mi] = smb + SMA + (uint32_t)(band*32 + mi*16 + (lane & 15))*512;
    int hiA = lane >> 4;
    int hiB = (lane >> 3) & 1;
    uint32_t bRow[4];
#pragma unroll
    for (int p = 0; p < 4; p++)
        bRow[p] = (uint32_t)(half*64 + p*16 + ((lane >> 4) & 1)*8 + (lane & 7))*512;

    CP_WAIT1();
    __syncthreads();

    for (int c = 0; c < NCHUNK; c++) {
        uint32_t bbase = smb + ((c & 1) ? SMB1 : SMB0);
        float acc[2][8][4];
#pragma unroll
        for (int mi = 0; mi < 2; mi++)
#pragma unroll
            for (int ni = 0; ni < 8; ni++)
#pragma unroll
                for (int k = 0; k < 4; k++) acc[mi][ni][k] = 0.0f;

#pragma unroll
        for (int kb = 0; kb < 16; kb++) {
            uint32_t a[2][4];
#pragma unroll
            for (int mi = 0; mi < 2; mi++) {
                uint32_t addr = aBase[mi] + (uint32_t)(((2*kb + hiA) ^ swz) << 4);
                ldsm4(a[mi][0], a[mi][1], a[mi][2], a[mi][3], addr);
            }
#pragma unroll
            for (int p = 0; p < 4; p++) {
                uint32_t b0, b1, b2, b3;
                uint32_t addr = bbase + bRow[p] + (uint32_t)(((2*kb + hiB) ^ swz) << 4);
                ldsm4(b0, b1, b2, b3, addr);
#pragma unroll
                for (int mi = 0; mi < 2; mi++) {
                    mma16816(acc[mi][2*p    ], a[mi][0], a[mi][1], a[mi][2], a[mi][3], b0, b1);
                    mma16816(acc[mi][2*p + 1], a[mi][0], a[mi][1], a[mi][2], a[mi][3], b2, b3);
                }
            }
        }

        int vb = c*128 + half*64 + (lane & 3)*2;
#pragma unroll
        for (int sl = 0; sl < 4; sl++) {
            int mi = sl >> 1, hi = sl & 1;
            int rowg = m0 + band*32 + mi*16 + hi*8 + (lane >> 2);
            float gm = -3.0e38f;
            float lv[16];
#pragma unroll
            for (int ni = 0; ni < 8; ni++) {
#pragma unroll
                for (int j = 0; j < 2; j++) {
                    int v = vb + ni*8 + j;
                    float val = acc[mi][ni][hi*2 + j] + bias_s[v];
                    if (v == vt[sl]) tgtlog[rowg] = val;
                    if (v == 3 && rowg < NROWS) eoslog[rowg] = val;
                    float e = (v < VSZ) ? val : -1.0e30f;
                    lv[ni*2 + j] = e;
                    gm = fmaxf(gm, e);
                }
            }
            float gs = 0.0f;
#pragma unroll
            for (int q = 0; q < 16; q++) gs += __expf(lv[q] - gm);
#pragma unroll
            for (int d = 1; d <= 2; d <<= 1) {
                float m2 = __shfl_xor_sync(0xffffffffu, gm, d);
                float s2 = __shfl_xor_sync(0xffffffffu, gs, d);
                float nm = fmaxf(gm, m2);
                gs = gs*__expf(gm - nm) + s2*__expf(m2 - nm);
                gm = nm;
            }
            float nm = fmaxf(Mv[sl], gm);
            Sv[sl] = Sv[sl]*__expf(Mv[sl] - nm) + gs*__expf(gm - nm);
            Mv[sl] = nm;
        }

        __syncthreads();
        if (c + 2 < NCHUNK)
            load_tile_async(smb + ((c & 1) ? SMB1 : SMB0),
                            bbf + (size_t)(c + 2)*128*ESZ, tid);
        CP_COMMIT();
        CP_WAIT1();
        __syncthreads();
    }

    float* smm = (float*)(sm + SMRED);
    float* sms = smm + 128;
    if (half == 0 && (lane & 3) == 0) {
#pragma unroll
        for (int sl = 0; sl < 4; sl++) {
            int rl = band*32 + (sl >> 1)*16 + (sl & 1)*8 + (lane >> 2);
            smm[rl] = Mv[sl]; sms[rl] = Sv[sl];
        }
    }
    __syncthreads();
    if (half == 1 && (lane & 3) == 0) {
#pragma unroll
        for (int sl = 0; sl < 4; sl++) {
            int rl = band*32 + (sl >> 1)*16 + (sl & 1)*8 + (lane >> 2);
            float m2 = smm[rl], s2 = sms[rl];
            float nm = fmaxf(Mv[sl], m2);
            float s = Sv[sl]*__expf(Mv[sl] - nm) + s2*__expf(m2 - nm);
            int rowg = m0 + rl;
            if (rowg < NROWS) lse[rowg] = nm + __logf(s);
        }
    }
}

// ---------------- segment log-probs -> logpy table ----------------
__global__ void logpy_kernel(const float* __restrict__ lse, const float* __restrict__ tgtlog,
                             const float* __restrict__ eoslog, const float* __restrict__ issing,
                             float* __restrict__ logpy)
{
    int idx = blockIdx.x*blockDim.x + threadIdx.x;
    if (idx >= (SSEG+1)*BSZ) return;
    int e = idx >> 5, b = idx & 31;
    if (e == 0) {
        logpy[b] = 0.0f;
        for (int k = 1; k < LSEG; k++) logpy[k*BSZ + b] = NEGINF;
        return;
    }
    int s = e - 1;
    int r = s*BSZ + b;
    float cum = 0.0f;
    float is_start = issing[(s+1)*BSZ + b];
    int jlen = SSEG - s; if (jlen > LSEG) jlen = LSEG;
    for (int k = 0; k < LSEG; k++) {
        int rowk = k*SB + r;
        float tlp = tgtlog[rowk] - lse[rowk];
        float segis = ((s+1+k) <= MSZ-1) ? issing[(s+1+k)*BSZ + b] : 0.0f;
        cum += tlp + ((k >= 1) ? segis : 0.0f);
        int rowe = (k+1)*SB + r;
        float eos = eoslog[rowe] - lse[rowe];
        float val = cum + ((k >= 1) ? is_start : 0.0f) + eos;
        if (k >= jlen) val = NEGINF;
        logpy[(e*LSEG + k)*BSZ + b] = val;
    }
}

// ---------------- final DP over segmentations ----------------
__global__ void dp_kernel(const float* __restrict__ logpy, const int* __restrict__ lengths,
                          float* __restrict__ out)
{
    int b = threadIdx.x;
    __shared__ float alph[MSZ-1][BSZ];
    float buf[LSEG] = {0.0f, NEGINF, NEGINF, NEGINF};
    alph[0][b] = 0.0f;
    for (int m = 1; m < MSZ-1; m++) {
        float v[LSEG], mx = -3.0e38f;
#pragma unroll
        for (int k = 0; k < LSEG; k++) {
            int e = m - k;
            float slp = (e >= 1) ? logpy[(e*LSEG + k)*BSZ + b] : NEGINF;
            v[k] = buf[k] + slp;
            mx = fmaxf(mx, v[k]);
        }
        float ssum = 0.0f;
#pragma unroll
        for (int k = 0; k < LSEG; k++) ssum += __expf(v[k]-mx);
        float a = mx + __logf(ssum);
        buf[3] = buf[2]; buf[2] = buf[1]; buf[1] = buf[0]; buf[0] = a;
        alph[m][b] = a;
    }
    int Lb = lengths[b];
    float nll = -alph[Lb-2][b];
    float tlen = (float)Lb;
#pragma unroll
    for (int off = 16; off; off >>= 1) {
        nll  += __shfl_down_sync(0xffffffffu, nll,  off);
        tlen += __shfl_down_sync(0xffffffffu, tlen, off);
    }
    if (b == 0) out[0] = nll / (tlen - 2.0f*BSZ);
}

// ---------------- launch ----------------
extern "C" void kernel_launch(void* const* d_in, const int* in_sizes, int n_in,
                              void* d_out, int out_size)
{
    const int*   x        = (const int*)  d_in[0];
    const int*   lengths  = (const int*)  d_in[1];
    const float* emb      = (const float*)d_in[2];
    const float* e2vb     = (const float*)d_in[3];
    const float* enc_Wih  = (const float*)d_in[4];
    const float* enc_Whh  = (const float*)d_in[5];
    const float* enc_bih  = (const float*)d_in[6];
    const float* enc_bhh  = (const float*)d_in[7];
    const float* enc_h0   = (const float*)d_in[8];
    const float* enc_c0   = (const float*)d_in[9];
    const float* dec_Wih  = (const float*)d_in[10];
    const float* dec_Whh  = (const float*)d_in[11];
    const float* dec_bih  = (const float*)d_in[12];
    const float* dec_bhh  = (const float*)d_in[13];
    const float* dht_W    = (const float*)d_in[14];
    const float* dht_b    = (const float*)d_in[15];
    const float* sos_W    = (const float*)d_in[16];
    const float* sos_b    = (const float*)d_in[17];
    float* out = (float*)d_out;

    float *p_issing, *p_enc_xg, *p_sos, *p_dxg0, *p_vxg, *p_gates, *p_dec_h, *p_dec_c;
    float *p_lse, *p_tgt, *p_eos, *p_logpy;
    __nv_bfloat16 *p_ibf, *p_eobf, *p_sosbf, *p_dhbf, *p_abf, *p_bbf;
    __nv_bfloat16 *p_wihe, *p_whhe, *p_wihd, *p_whhd, *p_sosw, *p_dhtw;
    cudaGetSymbolAddress((void**)&p_issing,  g_issing);
    cudaGetSymbolAddress((void**)&p_enc_xg,  g_enc_xg);
    cudaGetSymbolAddress((void**)&p_sos,     g_sos);
    cudaGetSymbolAddress((void**)&p_dxg0,    g_dxg0);
    cudaGetSymbolAddress((void**)&p_vxg,     g_vxg);
    cudaGetSymbolAddress((void**)&p_gates,   g_gates);
    cudaGetSymbolAddress((void**)&p_dec_h,   g_dec_h);
    cudaGetSymbolAddress((void**)&p_dec_c,   g_dec_c);
    cudaGetSymbolAddress((void**)&p_ibf,     g_ibf);
    cudaGetSymbolAddress((void**)&p_eobf,    g_eobf);
    cudaGetSymbolAddress((void**)&p_sosbf,   g_sosbf);
    cudaGetSymbolAddress((void**)&p_dhbf,    g_dhbf);
    cudaGetSymbolAddress((void**)&p_abf,     g_abf);
    cudaGetSymbolAddress((void**)&p_bbf,     g_bbf);
    cudaGetSymbolAddress((void**)&p_wihe,    g_wihe);
    cudaGetSymbolAddress((void**)&p_whhe,    g_whhe);
    cudaGetSymbolAddress((void**)&p_wihd,    g_wihd);
    cudaGetSymbolAddress((void**)&p_whhd,    g_whhd);
    cudaGetSymbolAddress((void**)&p_sosw,    g_sosw);
    cudaGetSymbolAddress((void**)&p_dhtw,    g_dhtw);
    cudaGetSymbolAddress((void**)&p_lse,     g_lse);
    cudaGetSymbolAddress((void**)&p_tgt,     g_tgtlog);
    cudaGetSymbolAddress((void**)&p_eos,     g_eoslog);
    cudaGetSymbolAddress((void**)&p_logpy,   g_logpy);

    cudaFuncSetAttribute(logits_mma, cudaFuncAttributeMaxDynamicSharedMemorySize, SMTOT);
    cudaFuncSetAttribute(gemm_mma,   cudaFuncAttributeMaxDynamicSharedMemorySize, GM_TOT);

    // 1. embed (bf16) + is_single ; emb -> bf16 ; weight conversions
    embed_kernel<<<MSZ*BSZ, 64>>>(x, emb, p_ibf, p_issing);
    cvt_emb<<<VPAD, 256>>>(emb, p_bbf);
    cvt_bf<<<(G4*ESZ + 255)/256, 256>>>(enc_Wih, p_wihe, G4*ESZ);
    cvt_bf<<<(G4*ESZ + 255)/256, 256>>>(enc_Whh, p_whhe, G4*ESZ);
    cvt_bf<<<(G4*ESZ + 255)/256, 256>>>(dec_Wih, p_wihd, G4*ESZ);
    cvt_bf<<<(G4*ESZ + 255)/256, 256>>>(dec_Whh, p_whhd, G4*ESZ);
    cvt_bf<<<(HSZ*ESZ + 255)/256, 256>>>(sos_W, p_sosw, HSZ*ESZ);
    cvt_bf<<<(HSZ*ESZ + 255)/256, 256>>>(dht_W, p_dhtw, HSZ*ESZ);
    // 2. encoder input gates (tensor core)
    gemm_mma<<<dim3(32, 8), 256, GM_TOT>>>(p_ibf, p_wihe, enc_bih, enc_bhh,
                                           p_enc_xg, nullptr, MSZ*BSZ, G4, 0);
    // 3. encoder recurrence (bf16 weights)
    enc_lstm<<<BSZ, 256>>>(p_enc_xg, p_whhe, enc_h0, enc_c0, p_eobf);
    // 4. sos (bf16 out for dxg0)
    gemm_mma<<<dim3(32, 2), 256, GM_TOT>>>(p_eobf, p_sosw, sos_b, nullptr,
                                           p_sos, p_sosbf, SB, HSZ, 0);
    // 5. dec_h0 = tanh(...) (bf16 out)
    gemm_mma<<<dim3(32, 2), 256, GM_TOT>>>(p_eobf, p_dhtw, dht_b, nullptr,
                                           p_dec_h, p_dhbf, SB, HSZ, 1);
    // 6. vocab input gates
    gemm_mma<<<dim3(32, 8), 256, GM_TOT>>>(p_bbf, p_wihd, dec_bih, dec_bhh,
                                           p_vxg, nullptr, VSZ, G4, 0);
    // 7. step-0 input gates from sos
    gemm_mma<<<dim3(32, 8), 256, GM_TOT>>>(p_sosbf, p_wihd, dec_bih, dec_bhh,
                                           p_dxg0, nullptr, SB, G4, 0);
    // 8. decoder: 5 sequential steps
    for (int t = 0; t <= LSEG; t++) {
        gemm_mma<<<dim3(32, 8), 256, GM_TOT>>>(p_dhbf, p_whhd, nullptr, nullptr,
                                               p_gates, nullptr, SB, G4, 2);
        dec_point<<<SB, 256>>>(p_gates, p_dxg0, p_vxg, x, dec_bih, dec_bhh,
                               p_dec_c, p_dhbf, p_abf, t);
    }
    // 9. bf16 mma.sync logits + fused LSE/target/EOS
    logits_mma<<<MTILES, 256, SMTOT>>>(p_abf, p_bbf, e2vb, x, p_lse, p_tgt, p_eos);
    // 10. segment log-probs table
    logpy_kernel<<<((SSEG+1)*BSZ + 127)/128, 128>>>(p_lse, p_tgt, p_eos, p_issing, p_logpy);
    // 11. DP + reduction -> scalar
    dp_kernel<<<1, 32>>>(p_logpy, lengths, out);

    (void)in_sizes; (void)n_in; (void)out_size;
}

// round 15
// speedup vs baseline: 5.0378x; 1.9946x over previous
#include <cuda_runtime.h>
#include <cuda_bf16.h>
#include <math.h>
#include <stddef.h>
#include <stdint.h>

// ---------------- problem constants ----------------
#define VSZ   4000
#define ESZ   256
#define HSZ   256
#define MSZ   128
#define BSZ   32
#define LSEG  4
#define SSEG  126            // M-2
#define SB    (SSEG*BSZ)     // 4032
#define G4    (4*HSZ)        // 1024
#define NROWS ((LSEG+1)*SB)  // 20160
#define MTILES 158           // ceil(20160/128)
#define NROWS_PAD (MTILES*128)
#define VPAD  4096
#define NCHUNK 32
#define NEGINF (-1.0e6f)

// ---------------- scratch ----------------
__device__ float g_issing [MSZ*BSZ];
__device__ float g_enc_xg [MSZ*BSZ*G4];
__device__ float g_sos    [4096*HSZ];
__device__ float g_dxg0   [4096*G4];
__device__ float g_vxg    [VPAD*G4];
__device__ float g_gates  [4096*G4];
__device__ float g_dec_h  [4096*HSZ];
__device__ float g_dec_c  [SB*HSZ];
__device__ int   g_flags  [BSZ*MSZ];             // per (b,t) arrival counters
__device__ float g_hbuf   [2*BSZ*HSZ];           // double-buffered encoder h
__device__ __nv_bfloat16 g_ibf  [MSZ*BSZ*ESZ];
__device__ __nv_bfloat16 g_eobf [MSZ*BSZ*ESZ];
__device__ __nv_bfloat16 g_sosbf[4096*ESZ];
__device__ __nv_bfloat16 g_dhbf [4096*ESZ];
__device__ __nv_bfloat16 g_abf[NROWS_PAD*ESZ];
__device__ __nv_bfloat16 g_bbf[VPAD*ESZ];
__device__ __nv_bfloat16 g_wihe[G4*ESZ];
__device__ __nv_bfloat16 g_whhe[G4*ESZ];
__device__ __nv_bfloat16 g_wihd[G4*ESZ];
__device__ __nv_bfloat16 g_whhd[G4*ESZ];
__device__ __nv_bfloat16 g_sosw[HSZ*ESZ];
__device__ __nv_bfloat16 g_dhtw[HSZ*ESZ];
__device__ float g_lse    [NROWS];
__device__ float g_tgtlog [NROWS];
__device__ float g_eoslog [NROWS];
__device__ float g_logpy  [(SSEG+1)*LSEG*BSZ];

__device__ __forceinline__ float sigmoidf(float x) { return 1.0f/(1.0f+__expf(-x)); }

// ================= mma.sync / ldmatrix / cp.async helpers ===
__device__ __forceinline__ uint32_t smem_u32(const void* p) {
    return (uint32_t)__cvta_generic_to_shared(p);
}
__device__ __forceinline__ void cp16(uint32_t dst, const void* src) {
    asm volatile("cp.async.cg.shared.global [%0], [%1], 16;" :: "r"(dst), "l"(src));
}
#define CP_COMMIT() asm volatile("cp.async.commit_group;" ::: "memory")
#define CP_WAIT1()  asm volatile("cp.async.wait_group 1;"  ::: "memory")
#define CP_WAIT0()  asm volatile("cp.async.wait_group 0;"  ::: "memory")

__device__ __forceinline__ void ldsm4(uint32_t& r0, uint32_t& r1, uint32_t& r2,
                                      uint32_t& r3, uint32_t addr) {
    asm volatile("ldmatrix.sync.aligned.m8n8.x4.shared.b16 {%0,%1,%2,%3}, [%4];"
                 : "=r"(r0), "=r"(r1), "=r"(r2), "=r"(r3) : "r"(addr));
}
__device__ __forceinline__ void mma16816(float* d, uint32_t a0, uint32_t a1,
                                         uint32_t a2, uint32_t a3,
                                         uint32_t b0, uint32_t b1) {
    asm volatile("mma.sync.aligned.m16n8k16.row.col.f32.bf16.bf16.f32 "
        "{%0,%1,%2,%3}, {%4,%5,%6,%7}, {%8,%9}, {%0,%1,%2,%3};"
        : "+f"(d[0]), "+f"(d[1]), "+f"(d[2]), "+f"(d[3])
        : "r"(a0), "r"(a1), "r"(a2), "r"(a3), "r"(b0), "r"(b1));
}

// Load a 128-row x 256-col bf16 tile (512B rows) gmem->smem with XOR-swizzle.
__device__ __forceinline__ void load_tile_async(uint32_t smbase,
                                                const __nv_bfloat16* g, int tid) {
#pragma unroll
    for (int l = 0; l < 16; l++) {
        int u = tid + l*256;
        int row = u >> 5, c = u & 31;
        uint32_t dst = smbase + row*512 + ((c ^ (row & 7)) << 4);
        cp16(dst, (const char*)g + (size_t)row*512 + c*16);
    }
}

// ---------------- embed (bf16) + is_single ----------------
__global__ void embed_kernel(const int* __restrict__ x, const float* __restrict__ emb,
                             __nv_bfloat16* __restrict__ ibf, float* __restrict__ issing)
{
    int row = blockIdx.x;
    int t = row >> 5, b = row & 31;
    int tok = x[b*MSZ + t];
    float4 v = ((const float4*)(emb + (size_t)tok*ESZ))[threadIdx.x];
    __nv_bfloat16* d = ibf + (size_t)row*ESZ + threadIdx.x*4;
    d[0] = __float2bfloat16(v.x); d[1] = __float2bfloat16(v.y);
    d[2] = __float2bfloat16(v.z); d[3] = __float2bfloat16(v.w);
    if (threadIdx.x == 0)
        issing[row] = (tok == 0 || tok == 1 || tok == 2) ? NEGINF : 0.0f;
}

// ---------------- emb -> bf16 (padded) ----------------
__global__ void cvt_emb(const float* __restrict__ emb, __nv_bfloat16* __restrict__ bbf)
{
    int v = blockIdx.x, c = threadIdx.x;
    bbf[(size_t)v*ESZ + c] = (v < VSZ) ? __float2bfloat16(emb[(size_t)v*ESZ + c])
                                       : __float2bfloat16(0.0f);
}

// ---------------- fused weight converts (+ encoder flag reset) ----------------
__global__ void cvt_w1(const float* __restrict__ s1, __nv_bfloat16* __restrict__ d1,
                       const float* __restrict__ s2, __nv_bfloat16* __restrict__ d2,
                       int n, int* __restrict__ flags, int nf)
{
    int i = blockIdx.x*256 + threadIdx.x;
    if (i < n) { d1[i] = __float2bfloat16(s1[i]); d2[i] = __float2bfloat16(s2[i]); }
    if (i < nf) flags[i] = 0;
}
__global__ void cvt_w2(const float* __restrict__ s1, __nv_bfloat16* __restrict__ d1,
                       const float* __restrict__ s2, __nv_bfloat16* __restrict__ d2,
                       int n, const float* __restrict__ s3, __nv_bfloat16* __restrict__ d3,
                       const float* __restrict__ s4, __nv_bfloat16* __restrict__ d4, int n2)
{
    int i = blockIdx.x*256 + threadIdx.x;
    if (i < n)  { d1[i] = __float2bfloat16(s1[i]); d2[i] = __float2bfloat16(s2[i]); }
    if (i < n2) { d3[i] = __float2bfloat16(s3[i]); d4[i] = __float2bfloat16(s4[i]); }
}

// ================ generic bf16 tensor-core GEMM: C = A @ W^T (+bias)[tanh] ===
#define GM_SMA 0
#define GM_SMW 65536
#define GM_TOT 131072

__global__ __launch_bounds__(256, 1)
void gemm_mma(const __nv_bfloat16* __restrict__ A, const __nv_bfloat16* __restrict__ W,
              const float* __restrict__ b1, const float* __restrict__ b2,
              float* __restrict__ C, __nv_bfloat16* __restrict__ Cbf,
              int R, int N, int epi)
{
    extern __shared__ char sm[];
    uint32_t smb = smem_u32(sm);
    int tid = threadIdx.x, wid = tid >> 5, lane = tid & 31;
    int band = wid & 3, half = wid >> 2;
    int m0 = blockIdx.x * 128, n0 = blockIdx.y * 128;

    load_tile_async(smb + GM_SMA, A + (size_t)m0*ESZ, tid);
    load_tile_async(smb + GM_SMW, W + (size_t)n0*ESZ, tid);
    CP_COMMIT();

    int swz = lane & 7;
    uint32_t aBase[2];
#pragma unroll
    for (int mi = 0; mi < 2; mi++)
        aBase[mi] = smb + GM_SMA + (uint32_t)(band*32 + mi*16 + (lane & 15))*512;
    int hiA = lane >> 4;
    int hiB = (lane >> 3) & 1;
    uint32_t bRow[4];
#pragma unroll
    for (int p = 0; p < 4; p++)
        bRow[p] = smb + GM_SMW + (uint32_t)(half*64 + p*16 + ((lane >> 4) & 1)*8 + (lane & 7))*512;

    float acc[2][8][4];
#pragma unroll
    for (int mi = 0; mi < 2; mi++)
#pragma unroll
        for (int ni = 0; ni < 8; ni++)
#pragma unroll
            for (int k = 0; k < 4; k++) acc[mi][ni][k] = 0.0f;

    CP_WAIT0();
    __syncthreads();

#pragma unroll
    for (int kb = 0; kb < 16; kb++) {
        uint32_t a[2][4];
#pragma unroll
        for (int mi = 0; mi < 2; mi++) {
            uint32_t addr = aBase[mi] + (uint32_t)(((2*kb + hiA) ^ swz) << 4);
            ldsm4(a[mi][0], a[mi][1], a[mi][2], a[mi][3], addr);
        }
#pragma unroll
        for (int p = 0; p < 4; p++) {
            uint32_t b0, b1r, b2r, b3;
            uint32_t addr = bRow[p] + (uint32_t)(((2*kb + hiB) ^ swz) << 4);
            ldsm4(b0, b1r, b2r, b3, addr);
#pragma unroll
            for (int mi = 0; mi < 2; mi++) {
                mma16816(acc[mi][2*p    ], a[mi][0], a[mi][1], a[mi][2], a[mi][3], b0, b1r);
                mma16816(acc[mi][2*p + 1], a[mi][0], a[mi][1], a[mi][2], a[mi][3], b2r, b3);
            }
        }
    }

    // epilogue
#pragma unroll
    for (int mi = 0; mi < 2; mi++) {
#pragma unroll
        for (int hi = 0; hi < 2; hi++) {
            int row = m0 + band*32 + mi*16 + hi*8 + (lane >> 2);
            if (row >= R) continue;
#pragma unroll
            for (int ni = 0; ni < 8; ni++) {
#pragma unroll
                for (int j = 0; j < 2; j++) {
                    int col = n0 + half*64 + ni*8 + (lane & 3)*2 + j;
                    float v = acc[mi][ni][hi*2 + j];
                    if (epi != 2) { v += b1[col]; if (b2) v += b2[col]; }
                    if (epi == 1) v = tanhf(v);
                    C[(size_t)row*N + col] = v;
                    if (Cbf) Cbf[(size_t)row*N + col] = __float2bfloat16(v);
                }
            }
        }
    }
}

// ---------------- encoder: 4 CTAs per batch element, L1-resident weights ----------------
__device__ __forceinline__ void fma2bf(float& acc, uint32_t u, float hlo, float hhi) {
    acc = fmaf(__uint_as_float(u << 16), hlo, acc);
    acc = fmaf(__uint_as_float(u & 0xffff0000u), hhi, acc);
}

__global__ __launch_bounds__(256)
void enc_lstm(const float* __restrict__ xg, const __nv_bfloat16* __restrict__ whhbf,
              const float* __restrict__ h0, const float* __restrict__ c0,
              __nv_bfloat16* __restrict__ eobf, int* __restrict__ flags,
              float* __restrict__ hbuf)
{
    int blk = blockIdx.x;
    int b = blk >> 2, q = blk & 3;        // 4 blocks per batch element
    int tid = threadIdx.x;
    int g = tid >> 6, jj = tid & 63;
    int grow = g*256 + q*64 + jj;         // this thread's gate row in [0,1024)
    __shared__ float hsh[HSZ];
    __shared__ float gsh[4][64];

    hsh[tid] = h0[tid];
    float c = (tid < 64) ? c0[q*64 + tid] : 0.0f;
    const uint4* wrow = (const uint4*)(whhbf + (size_t)grow*HSZ);
    __syncthreads();

    for (int t = 0; t < MSZ; t++) {
        float acc = xg[((size_t)t*BSZ + b)*G4 + grow];
#pragma unroll 8
        for (int kk = 0; kk < 32; kk++) {
            uint4 w = wrow[kk];
            float4 ha = *(const float4*)&hsh[kk*8];
            float4 hb = *(const float4*)&hsh[kk*8 + 4];
            fma2bf(acc, w.x, ha.x, ha.y);
            fma2bf(acc, w.y, ha.z, ha.w);
            fma2bf(acc, w.z, hb.x, hb.y);
            fma2bf(acc, w.w, hb.z, hb.w);
        }
        gsh[g][jj] = acc;
        __syncthreads();
        if (tid < 64) {
            int j2 = q*64 + tid;
            float gi = gsh[0][tid], gf = gsh[1][tid], gv = gsh[2][tid], go = gsh[3][tid];
            float cn = sigmoidf(gf)*c + sigmoidf(gi)*tanhf(gv);
            float hn = sigmoidf(go)*tanhf(cn);
            c = cn;
            // publish h slice to L2 (bypass L1 so peers' reads are never stale)
            asm volatile("st.global.cg.f32 [%0], %1;"
                :: "l"(hbuf + ((size_t)(t & 1)*BSZ + b)*HSZ + j2), "f"(hn) : "memory");
            eobf[((size_t)t*BSZ + b)*HSZ + j2] = __float2bfloat16(0.5f*hn);
        }
        __threadfence();
        __syncthreads();
        if (tid == 0) atomicAdd(&flags[b*MSZ + t], 1);
        if (t < MSZ-1) {
            if (tid == 0) {
                while (((volatile int*)flags)[b*MSZ + t] < 4) {}
            }
            __syncthreads();
            __threadfence();
            if (tid < 64) {
                float4 hv;
                const float* src = hbuf + ((size_t)(t & 1)*BSZ + b)*HSZ + tid*4;
                asm volatile("ld.global.cg.v4.f32 {%0,%1,%2,%3}, [%4];"
                    : "=f"(hv.x), "=f"(hv.y), "=f"(hv.z), "=f"(hv.w) : "l"(src));
                *(float4*)&hsh[tid*4] = hv;
            }
            __syncthreads();
        }
    }
}

// ---------------- decoder pointwise (writes bf16 h + dec_out) ----------------
__global__ void dec_point(const float* __restrict__ gates, const float* __restrict__ xg0,
                          const float* __restrict__ vxg, const int* __restrict__ x,
                          const float* __restrict__ bih, const float* __restrict__ bhh,
                          float* __restrict__ cc, __nv_bfloat16* __restrict__ hbf,
                          __nv_bfloat16* __restrict__ abf, int t)
{
    int r = blockIdx.x, j = threadIdx.x;
    int s = r >> 5, b = r & 31;
    const float* base = nullptr;
    if (t == 0) base = xg0 + (size_t)r*G4;
    else {
        int pos = s + t;
        if (pos <= MSZ-1) base = vxg + (size_t)x[b*MSZ + pos]*G4;
    }
    float xi, xf, xgv, xo;
    if (base) { xi = base[j]; xf = base[j+256]; xgv = base[j+512]; xo = base[j+768]; }
    else {     xi = bih[j]+bhh[j]; xf = bih[j+256]+bhh[j+256];
               xgv = bih[j+512]+bhh[j+512]; xo = bih[j+768]+bhh[j+768]; }
    const float* gr = gates + (size_t)r*G4;
    float gi = gr[j] + xi, gf = gr[j+256] + xf, gg = gr[j+512] + xgv, go = gr[j+768] + xo;
    float cp = (t == 0) ? 0.0f : cc[(size_t)r*HSZ + j];
    float cn = sigmoidf(gf)*cp + sigmoidf(gi)*tanhf(gg);
    float hn = sigmoidf(go)*tanhf(cn);
    cc[(size_t)r*HSZ + j] = cn;
    __nv_bfloat16 hb = __float2bfloat16(hn);
    hbf[(size_t)r*HSZ + j] = hb;
    abf[((size_t)t*SB + r)*ESZ + j] = hb;
}

// ================ bf16 mma.sync logits + fused online LSE ===
#define SMA    0
#define SMB0   65536
#define SMB1   131072
#define SMBIAS 196608
#define SMRED  212992
#define SMTOT  214016

__global__ __launch_bounds__(256, 1)
void logits_mma(const __nv_bfloat16* __restrict__ abf, const __nv_bfloat16* __restrict__ bbf,
                const float* __restrict__ e2vb, const int* __restrict__ x,
                float* __restrict__ lse, float* __restrict__ tgtlog,
                float* __restrict__ eoslog)
{
    extern __shared__ char sm[];
    uint32_t smb = smem_u32(sm);
    int tid = threadIdx.x, wid = tid >> 5, lane = tid & 31;
    int band = wid & 3, half = wid >> 2;
    int m0 = blockIdx.x * 128;

    load_tile_async(smb + SMA, abf + (size_t)m0*ESZ, tid);
    CP_COMMIT();
    load_tile_async(smb + SMB0, bbf, tid);
    CP_COMMIT();
    load_tile_async(smb + SMB1, bbf + (size_t)128*ESZ, tid);
    CP_COMMIT();
    float* bias_s = (float*)(sm + SMBIAS);
#pragma unroll
    for (int l = 0; l < 16; l++) {
        int i = tid + l*256;
        bias_s[i] = (i < VSZ) ? e2vb[i] : 0.0f;
    }

    int vt[4];
    float Mv[4], Sv[4];
#pragma unroll
    for (int sl = 0; sl < 4; sl++) {
        int rl = band*32 + (sl >> 1)*16 + (sl & 1)*8 + (lane >> 2);
        int row = m0 + rl;
        vt[sl] = -1;
        if (row < NROWS) {
            int t = row / SB; int rr = row % SB; int s = rr >> 5; int b = rr & 31;
            if (t < LSEG) { int pos = s + 1 + t; vt[sl] = (pos <= MSZ-1) ? x[b*MSZ + pos] : 0; }
        }
        Mv[sl] = -3.0e38f; Sv[sl] = 0.0f;
    }

    int swz = lane & 7;
    uint32_t aBase[2];
#pragma unroll
    for (int mi = 0; mi < 2; mi++)
        aBase[mi] = smb + SMA + (uint32_t)(band*32 + mi*16 + (lane & 15))*512;
    int hiA = lane >> 4;
    int hiB = (lane >> 3) & 1;
    uint32_t bRow[4];
#pragma unroll
    for (int p = 0; p < 4; p++)
        bRow[p] = (uint32_t)(half*64 + p*16 + ((lane >> 4) & 1)*8 + (lane & 7))*512;

    CP_WAIT1();
    __syncthreads();

    for (int c = 0; c < NCHUNK; c++) {
        uint32_t bbase = smb + ((c & 1) ? SMB1 : SMB0);
        float acc[2][8][4];
#pragma unroll
        for (int mi = 0; mi < 2; mi++)
#pragma unroll
            for (int ni = 0; ni < 8; ni++)
#pragma unroll
                for (int k = 0; k < 4; k++) acc[mi][ni][k] = 0.0f;

#pragma unroll
        for (int kb = 0; kb < 16; kb++) {
            uint32_t a[2][4];
#pragma unroll
            for (int mi = 0; mi < 2; mi++) {
                uint32_t addr = aBase[mi] + (uint32_t)(((2*kb + hiA) ^ swz) << 4);
                ldsm4(a[mi][0], a[mi][1], a[mi][2], a[mi][3], addr);
            }
#pragma unroll
            for (int p = 0; p < 4; p++) {
                uint32_t b0, b1, b2, b3;
                uint32_t addr = bbase + bRow[p] + (uint32_t)(((2*kb + hiB) ^ swz) << 4);
                ldsm4(b0, b1, b2, b3, addr);
#pragma unroll
                for (int mi = 0; mi < 2; mi++) {
                    mma16816(acc[mi][2*p    ], a[mi][0], a[mi][1], a[mi][2], a[mi][3], b0, b1);
                    mma16816(acc[mi][2*p + 1], a[mi][0], a[mi][1], a[mi][2], a[mi][3], b2, b3);
                }
            }
        }

        int vb = c*128 + half*64 + (lane & 3)*2;
#pragma unroll
        for (int sl = 0; sl < 4; sl++) {
            int mi = sl >> 1, hi = sl & 1;
            int rowg = m0 + band*32 + mi*16 + hi*8 + (lane >> 2);
            float gm = -3.0e38f;
            float lv[16];
#pragma unroll
            for (int ni = 0; ni < 8; ni++) {
#pragma unroll
                for (int j = 0; j < 2; j++) {
                    int v = vb + ni*8 + j;
                    float val = acc[mi][ni][hi*2 + j] + bias_s[v];
                    if (v == vt[sl]) tgtlog[rowg] = val;
                    if (v == 3 && rowg < NROWS) eoslog[rowg] = val;
                    float e = (v < VSZ) ? val : -1.0e30f;
                    lv[ni*2 + j] = e;
                    gm = fmaxf(gm, e);
                }
            }
            float gs = 0.0f;
#pragma unroll
            for (int q = 0; q < 16; q++) gs += __expf(lv[q] - gm);
#pragma unroll
            for (int d = 1; d <= 2; d <<= 1) {
                float m2 = __shfl_xor_sync(0xffffffffu, gm, d);
                float s2 = __shfl_xor_sync(0xffffffffu, gs, d);
                float nm = fmaxf(gm, m2);
                gs = gs*__expf(gm - nm) + s2*__expf(m2 - nm);
                gm = nm;
            }
            float nm = fmaxf(Mv[sl], gm);
            Sv[sl] = Sv[sl]*__expf(Mv[sl] - nm) + gs*__expf(gm - nm);
            Mv[sl] = nm;
        }

        __syncthreads();
        if (c + 2 < NCHUNK)
            load_tile_async(smb + ((c & 1) ? SMB1 : SMB0),
                            bbf + (size_t)(c + 2)*128*ESZ, tid);
        CP_COMMIT();
        CP_WAIT1();
        __syncthreads();
    }

    float* smm = (float*)(sm + SMRED);
    float* sms = smm + 128;
    if (half == 0 && (lane & 3) == 0) {
#pragma unroll
        for (int sl = 0; sl < 4; sl++) {
            int rl = band*32 + (sl >> 1)*16 + (sl & 1)*8 + (lane >> 2);
            smm[rl] = Mv[sl]; sms[rl] = Sv[sl];
        }
    }
    __syncthreads();
    if (half == 1 && (lane & 3) == 0) {
#pragma unroll
        for (int sl = 0; sl < 4; sl++) {
            int rl = band*32 + (sl >> 1)*16 + (sl & 1)*8 + (lane >> 2);
            float m2 = smm[rl], s2 = sms[rl];
            float nm = fmaxf(Mv[sl], m2);
            float s = Sv[sl]*__expf(Mv[sl] - nm) + s2*__expf(m2 - nm);
            int rowg = m0 + rl;
            if (rowg < NROWS) lse[rowg] = nm + __logf(s);
        }
    }
}

// ---------------- segment log-probs -> logpy table ----------------
__global__ void logpy_kernel(const float* __restrict__ lse, const float* __restrict__ tgtlog,
                             const float* __restrict__ eoslog, const float* __restrict__ issing,
                             float* __restrict__ logpy)
{
    int idx = blockIdx.x*blockDim.x + threadIdx.x;
    if (idx >= (SSEG+1)*BSZ) return;
    int e = idx >> 5, b = idx & 31;
    if (e == 0) {
        logpy[b] = 0.0f;
        for (int k = 1; k < LSEG; k++) logpy[k*BSZ + b] = NEGINF;
        return;
    }
    int s = e - 1;
    int r = s*BSZ + b;
    float cum = 0.0f;
    float is_start = issing[(s+1)*BSZ + b];
    int jlen = SSEG - s; if (jlen > LSEG) jlen = LSEG;
    for (int k = 0; k < LSEG; k++) {
        int rowk = k*SB + r;
        float tlp = tgtlog[rowk] - lse[rowk];
        float segis = ((s+1+k) <= MSZ-1) ? issing[(s+1+k)*BSZ + b] : 0.0f;
        cum += tlp + ((k >= 1) ? segis : 0.0f);
        int rowe = (k+1)*SB + r;
        float eos = eoslog[rowe] - lse[rowe];
        float val = cum + ((k >= 1) ? is_start : 0.0f) + eos;
        if (k >= jlen) val = NEGINF;
        logpy[(e*LSEG + k)*BSZ + b] = val;
    }
}

// ---------------- final DP over segmentations ----------------
__global__ void dp_kernel(const float* __restrict__ logpy, const int* __restrict__ lengths,
                          float* __restrict__ out)
{
    int b = threadIdx.x;
    __shared__ float alph[MSZ-1][BSZ];
    float buf[LSEG] = {0.0f, NEGINF, NEGINF, NEGINF};
    alph[0][b] = 0.0f;
    for (int m = 1; m < MSZ-1; m++) {
        float v[LSEG], mx = -3.0e38f;
#pragma unroll
        for (int k = 0; k < LSEG; k++) {
            int e = m - k;
            float slp = (e >= 1) ? logpy[(e*LSEG + k)*BSZ + b] : NEGINF;
            v[k] = buf[k] + slp;
            mx = fmaxf(mx, v[k]);
        }
        float ssum = 0.0f;
#pragma unroll
        for (int k = 0; k < LSEG; k++) ssum += __expf(v[k]-mx);
        float a = mx + __logf(ssum);
        buf[3] = buf[2]; buf[2] = buf[1]; buf[1] = buf[0]; buf[0] = a;
        alph[m][b] = a;
    }
    int Lb = lengths[b];
    float nll = -alph[Lb-2][b];
    float tlen = (float)Lb;
#pragma unroll
    for (int off = 16; off; off >>= 1) {
        nll  += __shfl_down_sync(0xffffffffu, nll,  off);
        tlen += __shfl_down_sync(0xffffffffu, tlen, off);
    }
    if (b == 0) out[0] = nll / (tlen - 2.0f*BSZ);
}

// ---------------- launch ----------------
extern "C" void kernel_launch(void* const* d_in, const int* in_sizes, int n_in,
                              void* d_out, int out_size)
{
    const int*   x        = (const int*)  d_in[0];
    const int*   lengths  = (const int*)  d_in[1];
    const float* emb      = (const float*)d_in[2];
    const float* e2vb     = (const float*)d_in[3];
    const float* enc_Wih  = (const float*)d_in[4];
    const float* enc_Whh  = (const float*)d_in[5];
    const float* enc_bih  = (const float*)d_in[6];
    const float* enc_bhh  = (const float*)d_in[7];
    const float* enc_h0   = (const float*)d_in[8];
    const float* enc_c0   = (const float*)d_in[9];
    const float* dec_Wih  = (const float*)d_in[10];
    const float* dec_Whh  = (const float*)d_in[11];
    const float* dec_bih  = (const float*)d_in[12];
    const float* dec_bhh  = (const float*)d_in[13];
    const float* dht_W    = (const float*)d_in[14];
    const float* dht_b    = (const float*)d_in[15];
    const float* sos_W    = (const float*)d_in[16];
    const float* sos_b    = (const float*)d_in[17];
    float* out = (float*)d_out;

    float *p_issing, *p_enc_xg, *p_sos, *p_dxg0, *p_vxg, *p_gates, *p_dec_h, *p_dec_c;
    float *p_lse, *p_tgt, *p_eos, *p_logpy, *p_hbuf;
    int *p_flags;
    __nv_bfloat16 *p_ibf, *p_eobf, *p_sosbf, *p_dhbf, *p_abf, *p_bbf;
    __nv_bfloat16 *p_wihe, *p_whhe, *p_wihd, *p_whhd, *p_sosw, *p_dhtw;
    cudaGetSymbolAddress((void**)&p_issing,  g_issing);
    cudaGetSymbolAddress((void**)&p_enc_xg,  g_enc_xg);
    cudaGetSymbolAddress((void**)&p_sos,     g_sos);
    cudaGetSymbolAddress((void**)&p_dxg0,    g_dxg0);
    cudaGetSymbolAddress((void**)&p_vxg,     g_vxg);
    cudaGetSymbolAddress((void**)&p_gates,   g_gates);
    cudaGetSymbolAddress((void**)&p_dec_h,   g_dec_h);
    cudaGetSymbolAddress((void**)&p_dec_c,   g_dec_c);
    cudaGetSymbolAddress((void**)&p_flags,   g_flags);
    cudaGetSymbolAddress((void**)&p_hbuf,    g_hbuf);
    cudaGetSymbolAddress((void**)&p_ibf,     g_ibf);
    cudaGetSymbolAddress((void**)&p_eobf,    g_eobf);
    cudaGetSymbolAddress((void**)&p_sosbf,   g_sosbf);
    cudaGetSymbolAddress((void**)&p_dhbf,    g_dhbf);
    cudaGetSymbolAddress((void**)&p_abf,     g_abf);
    cudaGetSymbolAddress((void**)&p_bbf,     g_bbf);
    cudaGetSymbolAddress((void**)&p_wihe,    g_wihe);
    cudaGetSymbolAddress((void**)&p_whhe,    g_whhe);
    cudaGetSymbolAddress((void**)&p_wihd,    g_wihd);
    cudaGetSymbolAddress((void**)&p_whhd,    g_whhd);
    cudaGetSymbolAddress((void**)&p_sosw,    g_sosw);
    cudaGetSymbolAddress((void**)&p_dhtw,    g_dhtw);
    cudaGetSymbolAddress((void**)&p_lse,     g_lse);
    cudaGetSymbolAddress((void**)&p_tgt,     g_tgtlog);
    cudaGetSymbolAddress((void**)&p_eos,     g_eoslog);
    cudaGetSymbolAddress((void**)&p_logpy,   g_logpy);

    cudaFuncSetAttribute(logits_mma, cudaFuncAttributeMaxDynamicSharedMemorySize, SMTOT);
    cudaFuncSetAttribute(gemm_mma,   cudaFuncAttributeMaxDynamicSharedMemorySize, GM_TOT);

    // launch order arranged so ncu (-s 5 -c 1) captures enc_lstm (launch #6)
    // 1. embed (bf16) + is_single
    embed_kernel<<<MSZ*BSZ, 64>>>(x, emb, p_ibf, p_issing);
    // 2. emb -> bf16
    cvt_emb<<<VPAD, 256>>>(emb, p_bbf);
    // 3. encoder weight converts + flag reset
    cvt_w1<<<(G4*ESZ + 255)/256, 256>>>(enc_Wih, p_wihe, enc_Whh, p_whhe,
                                        G4*ESZ, p_flags, BSZ*MSZ);
    // 4. decoder/sos/dht weight converts
    cvt_w2<<<(G4*ESZ + 255)/256, 256>>>(dec_Wih, p_wihd, dec_Whh, p_whhd, G4*ESZ,
                                        sos_W, p_sosw, dht_W, p_dhtw, HSZ*ESZ);
    // 5. encoder input gates (tensor core)
    gemm_mma<<<dim3(32, 8), 256, GM_TOT>>>(p_ibf, p_wihe, enc_bih, enc_bhh,
                                           p_enc_xg, nullptr, MSZ*BSZ, G4, 0);
    // 6. encoder recurrence: 4 CTAs per batch element, L1-resident weights
    enc_lstm<<<BSZ*4, 256>>>(p_enc_xg, p_whhe, enc_h0, enc_c0, p_eobf,
                             p_flags, p_hbuf);
    // 7. sos (bf16 out for dxg0)
    gemm_mma<<<dim3(32, 2), 256, GM_TOT>>>(p_eobf, p_sosw, sos_b, nullptr,
                                           p_sos, p_sosbf, SB, HSZ, 0);
    // 8. dec_h0 = tanh(...) (bf16 out)
    gemm_mma<<<dim3(32, 2), 256, GM_TOT>>>(p_eobf, p_dhtw, dht_b, nullptr,
                                           p_dec_h, p_dhbf, SB, HSZ, 1);
    // 9. vocab input gates
    gemm_mma<<<dim3(32, 8), 256, GM_TOT>>>(p_bbf, p_wihd, dec_bih, dec_bhh,
                                           p_vxg, nullptr, VSZ, G4, 0);
    // 10. step-0 input gates from sos
    gemm_mma<<<dim3(32, 8), 256, GM_TOT>>>(p_sosbf, p_wihd, dec_bih, dec_bhh,
                                           p_dxg0, nullptr, SB, G4, 0);
    // 11. decoder: 5 sequential steps
    for (int t = 0; t <= LSEG; t++) {
        gemm_mma<<<dim3(32, 8), 256, GM_TOT>>>(p_dhbf, p_whhd, nullptr, nullptr,
                                               p_gates, nullptr, SB, G4, 2);
        dec_point<<<SB, 256>>>(p_gates, p_dxg0, p_vxg, x, dec_bih, dec_bhh,
                               p_dec_c, p_dhbf, p_abf, t);
    }
    // 12. bf16 mma.sync logits + fused LSE/target/EOS
    logits_mma<<<MTILES, 256, SMTOT>>>(p_abf, p_bbf, e2vb, x, p_lse, p_tgt, p_eos);
    // 13. segment log-probs table
    logpy_kernel<<<((SSEG+1)*BSZ + 127)/128, 128>>>(p_lse, p_tgt, p_eos, p_issing, p_logpy);
    // 14. DP + reduction -> scalar
    dp_kernel<<<1, 32>>>(p_logpy, lengths, out);

    (void)in_sizes; (void)n_in; (void)out_size;
}

// round 16
// speedup vs baseline: 5.1631x; 1.0249x over previous
#include <cuda_runtime.h>
#include <cuda_bf16.h>
#include <math.h>
#include <stddef.h>
#include <stdint.h>

// ---------------- problem constants ----------------
#define VSZ   4000
#define ESZ   256
#define HSZ   256
#define MSZ   128
#define BSZ   32
#define LSEG  4
#define SSEG  126            // M-2
#define SB    (SSEG*BSZ)     // 4032
#define G4    (4*HSZ)        // 1024
#define NROWS ((LSEG+1)*SB)  // 20160
#define MTILES 158           // ceil(20160/128)
#define NROWS_PAD (MTILES*128)
#define VPAD  4096
#define VHALF 2048
#define NCH_H 16             // chunks per vocab half
#define NEGINF (-1.0e6f)

// ---------------- scratch ----------------
__device__ float g_issing [MSZ*BSZ];
__device__ float g_enc_xg [MSZ*BSZ*G4];
__device__ float g_sos    [4096*HSZ];
__device__ float g_dxg0   [4096*G4];
__device__ float g_vxg    [VPAD*G4];
__device__ float g_gates  [4096*G4];
__device__ float g_dec_h  [4096*HSZ];
__device__ float g_dec_c  [SB*HSZ];
__device__ int   g_flags  [BSZ*MSZ];             // per (b,t) arrival counters
__device__ float g_hbuf   [2*BSZ*HSZ];           // double-buffered encoder h
__device__ float g_pm     [2*NROWS_PAD];         // per-half partial max
__device__ float g_ps     [2*NROWS_PAD];         // per-half partial sum
__device__ __nv_bfloat16 g_ibf  [MSZ*BSZ*ESZ];
__device__ __nv_bfloat16 g_eobf [MSZ*BSZ*ESZ];
__device__ __nv_bfloat16 g_sosbf[4096*ESZ];
__device__ __nv_bfloat16 g_dhbf [4096*ESZ];
__device__ __nv_bfloat16 g_abf[NROWS_PAD*ESZ];
__device__ __nv_bfloat16 g_bbf[VPAD*ESZ];
__device__ __nv_bfloat16 g_wihe[G4*ESZ];
__device__ __nv_bfloat16 g_whhe[G4*ESZ];
__device__ __nv_bfloat16 g_wihd[G4*ESZ];
__device__ __nv_bfloat16 g_whhd[G4*ESZ];
__device__ __nv_bfloat16 g_sosw[HSZ*ESZ];
__device__ __nv_bfloat16 g_dhtw[HSZ*ESZ];
__device__ float g_lse    [NROWS];
__device__ float g_tgtlog [NROWS];
__device__ float g_eoslog [NROWS];
__device__ float g_logpy  [(SSEG+1)*LSEG*BSZ];

__device__ __forceinline__ float sigmoidf(float x) { return 1.0f/(1.0f+__expf(-x)); }

// ================= mma.sync / ldmatrix / cp.async helpers ===
__device__ __forceinline__ uint32_t smem_u32(const void* p) {
    return (uint32_t)__cvta_generic_to_shared(p);
}
__device__ __forceinline__ void cp16(uint32_t dst, const void* src) {
    asm volatile("cp.async.cg.shared.global [%0], [%1], 16;" :: "r"(dst), "l"(src));
}
#define CP_COMMIT() asm volatile("cp.async.commit_group;" ::: "memory")
#define CP_WAIT1()  asm volatile("cp.async.wait_group 1;"  ::: "memory")
#define CP_WAIT0()  asm volatile("cp.async.wait_group 0;"  ::: "memory")

__device__ __forceinline__ void ldsm4(uint32_t& r0, uint32_t& r1, uint32_t& r2,
                                      uint32_t& r3, uint32_t addr) {
    asm volatile("ldmatrix.sync.aligned.m8n8.x4.shared.b16 {%0,%1,%2,%3}, [%4];"
                 : "=r"(r0), "=r"(r1), "=r"(r2), "=r"(r3) : "r"(addr));
}
__device__ __forceinline__ void mma16816(float* d, uint32_t a0, uint32_t a1,
                                         uint32_t a2, uint32_t a3,
                                         uint32_t b0, uint32_t b1) {
    asm volatile("mma.sync.aligned.m16n8k16.row.col.f32.bf16.bf16.f32 "
        "{%0,%1,%2,%3}, {%4,%5,%6,%7}, {%8,%9}, {%0,%1,%2,%3};"
        : "+f"(d[0]), "+f"(d[1]), "+f"(d[2]), "+f"(d[3])
        : "r"(a0), "r"(a1), "r"(a2), "r"(a3), "r"(b0), "r"(b1));
}

// Load a 128-row x 256-col bf16 tile (512B rows) gmem->smem with XOR-swizzle.
__device__ __forceinline__ void load_tile_async(uint32_t smbase,
                                                const __nv_bfloat16* g, int tid) {
#pragma unroll
    for (int l = 0; l < 16; l++) {
        int u = tid + l*256;
        int row = u >> 5, c = u & 31;
        uint32_t dst = smbase + row*512 + ((c ^ (row & 7)) << 4);
        cp16(dst, (const char*)g + (size_t)row*512 + c*16);
    }
}

// ---------------- embed (bf16) + is_single ----------------
__global__ void embed_kernel(const int* __restrict__ x, const float* __restrict__ emb,
                             __nv_bfloat16* __restrict__ ibf, float* __restrict__ issing)
{
    int row = blockIdx.x;
    int t = row >> 5, b = row & 31;
    int tok = x[b*MSZ + t];
    float4 v = ((const float4*)(emb + (size_t)tok*ESZ))[threadIdx.x];
    __nv_bfloat16* d = ibf + (size_t)row*ESZ + threadIdx.x*4;
    d[0] = __float2bfloat16(v.x); d[1] = __float2bfloat16(v.y);
    d[2] = __float2bfloat16(v.z); d[3] = __float2bfloat16(v.w);
    if (threadIdx.x == 0)
        issing[row] = (tok == 0 || tok == 1 || tok == 2) ? NEGINF : 0.0f;
}

// ---------------- emb -> bf16 (padded) ----------------
__global__ void cvt_emb(const float* __restrict__ emb, __nv_bfloat16* __restrict__ bbf)
{
    int v = blockIdx.x, c = threadIdx.x;
    bbf[(size_t)v*ESZ + c] = (v < VSZ) ? __float2bfloat16(emb[(size_t)v*ESZ + c])
                                       : __float2bfloat16(0.0f);
}

// ---------------- fused weight converts (+ encoder flag reset) ----------------
__global__ void cvt_w1(const float* __restrict__ s1, __nv_bfloat16* __restrict__ d1,
                       const float* __restrict__ s2, __nv_bfloat16* __restrict__ d2,
                       int n, int* __restrict__ flags, int nf)
{
    int i = blockIdx.x*256 + threadIdx.x;
    if (i < n) { d1[i] = __float2bfloat16(s1[i]); d2[i] = __float2bfloat16(s2[i]); }
    if (i < nf) flags[i] = 0;
}
__global__ void cvt_w2(const float* __restrict__ s1, __nv_bfloat16* __restrict__ d1,
                       const float* __restrict__ s2, __nv_bfloat16* __restrict__ d2,
                       int n, const float* __restrict__ s3, __nv_bfloat16* __restrict__ d3,
                       const float* __restrict__ s4, __nv_bfloat16* __restrict__ d4, int n2)
{
    int i = blockIdx.x*256 + threadIdx.x;
    if (i < n)  { d1[i] = __float2bfloat16(s1[i]); d2[i] = __float2bfloat16(s2[i]); }
    if (i < n2) { d3[i] = __float2bfloat16(s3[i]); d4[i] = __float2bfloat16(s4[i]); }
}

// ================ generic bf16 tensor-core GEMM: C = A @ W^T (+bias)[tanh] ===
#define GM_SMA 0
#define GM_SMW 65536
#define GM_TOT 131072

__global__ __launch_bounds__(256, 1)
void gemm_mma(const __nv_bfloat16* __restrict__ A, const __nv_bfloat16* __restrict__ W,
              const float* __restrict__ b1, const float* __restrict__ b2,
              float* __restrict__ C, __nv_bfloat16* __restrict__ Cbf,
              int R, int N, int epi)
{
    extern __shared__ char sm[];
    uint32_t smb = smem_u32(sm);
    int tid = threadIdx.x, wid = tid >> 5, lane = tid & 31;
    int band = wid & 3, half = wid >> 2;
    int m0 = blockIdx.x * 128, n0 = blockIdx.y * 128;

    load_tile_async(smb + GM_SMA, A + (size_t)m0*ESZ, tid);
    load_tile_async(smb + GM_SMW, W + (size_t)n0*ESZ, tid);
    CP_COMMIT();

    int swz = lane & 7;
    uint32_t aBase[2];
#pragma unroll
    for (int mi = 0; mi < 2; mi++)
        aBase[mi] = smb + GM_SMA + (uint32_t)(band*32 + mi*16 + (lane & 15))*512;
    int hiA = lane >> 4;
    int hiB = (lane >> 3) & 1;
    uint32_t bRow[4];
#pragma unroll
    for (int p = 0; p < 4; p++)
        bRow[p] = smb + GM_SMW + (uint32_t)(half*64 + p*16 + ((lane >> 4) & 1)*8 + (lane & 7))*512;

    float acc[2][8][4];
#pragma unroll
    for (int mi = 0; mi < 2; mi++)
#pragma unroll
        for (int ni = 0; ni < 8; ni++)
#pragma unroll
            for (int k = 0; k < 4; k++) acc[mi][ni][k] = 0.0f;

    CP_WAIT0();
    __syncthreads();

#pragma unroll
    for (int kb = 0; kb < 16; kb++) {
        uint32_t a[2][4];
#pragma unroll
        for (int mi = 0; mi < 2; mi++) {
            uint32_t addr = aBase[mi] + (uint32_t)(((2*kb + hiA) ^ swz) << 4);
            ldsm4(a[mi][0], a[mi][1], a[mi][2], a[mi][3], addr);
        }
#pragma unroll
        for (int p = 0; p < 4; p++) {
            uint32_t b0, b1r, b2r, b3;
            uint32_t addr = bRow[p] + (uint32_t)(((2*kb + hiB) ^ swz) << 4);
            ldsm4(b0, b1r, b2r, b3, addr);
#pragma unroll
            for (int mi = 0; mi < 2; mi++) {
                mma16816(acc[mi][2*p    ], a[mi][0], a[mi][1], a[mi][2], a[mi][3], b0, b1r);
                mma16816(acc[mi][2*p + 1], a[mi][0], a[mi][1], a[mi][2], a[mi][3], b2r, b3);
            }
        }
    }

    // epilogue
#pragma unroll
    for (int mi = 0; mi < 2; mi++) {
#pragma unroll
        for (int hi = 0; hi < 2; hi++) {
            int row = m0 + band*32 + mi*16 + hi*8 + (lane >> 2);
            if (row >= R) continue;
#pragma unroll
            for (int ni = 0; ni < 8; ni++) {
#pragma unroll
                for (int j = 0; j < 2; j++) {
                    int col = n0 + half*64 + ni*8 + (lane & 3)*2 + j;
                    float v = acc[mi][ni][hi*2 + j];
                    if (epi != 2) { v += b1[col]; if (b2) v += b2[col]; }
                    if (epi == 1) v = tanhf(v);
                    C[(size_t)row*N + col] = v;
                    if (Cbf) Cbf[(size_t)row*N + col] = __float2bfloat16(v);
                }
            }
        }
    }
}

// ---------------- encoder: 4 CTAs per batch element, L1-resident weights ----------------
__device__ __forceinline__ void fma2bf(float& acc, uint32_t u, float hlo, float hhi) {
    acc = fmaf(__uint_as_float(u << 16), hlo, acc);
    acc = fmaf(__uint_as_float(u & 0xffff0000u), hhi, acc);
}

__global__ __launch_bounds__(256)
void enc_lstm(const float* __restrict__ xg, const __nv_bfloat16* __restrict__ whhbf,
              const float* __restrict__ h0, const float* __restrict__ c0,
              __nv_bfloat16* __restrict__ eobf, int* __restrict__ flags,
              float* __restrict__ hbuf)
{
    int blk = blockIdx.x;
    int b = blk >> 2, q = blk & 3;        // 4 blocks per batch element
    int tid = threadIdx.x;
    int g = tid >> 6, jj = tid & 63;
    int grow = g*256 + q*64 + jj;         // this thread's gate row in [0,1024)
    __shared__ float hsh[HSZ];
    __shared__ float gsh[4][64];

    hsh[tid] = h0[tid];
    float c = (tid < 64) ? c0[q*64 + tid] : 0.0f;
    const uint4* wrow = (const uint4*)(whhbf + (size_t)grow*HSZ);
    __syncthreads();

    for (int t = 0; t < MSZ; t++) {
        float acc = xg[((size_t)t*BSZ + b)*G4 + grow];
#pragma unroll 8
        for (int kk = 0; kk < 32; kk++) {
            uint4 w = wrow[kk];
            float4 ha = *(const float4*)&hsh[kk*8];
            float4 hb = *(const float4*)&hsh[kk*8 + 4];
            fma2bf(acc, w.x, ha.x, ha.y);
            fma2bf(acc, w.y, ha.z, ha.w);
            fma2bf(acc, w.z, hb.x, hb.y);
            fma2bf(acc, w.w, hb.z, hb.w);
        }
        gsh[g][jj] = acc;
        __syncthreads();
        if (tid < 64) {
            int j2 = q*64 + tid;
            float gi = gsh[0][tid], gf = gsh[1][tid], gv = gsh[2][tid], go = gsh[3][tid];
            float cn = sigmoidf(gf)*c + sigmoidf(gi)*tanhf(gv);
            float hn = sigmoidf(go)*tanhf(cn);
            c = cn;
            asm volatile("st.global.cg.f32 [%0], %1;"
                :: "l"(hbuf + ((size_t)(t & 1)*BSZ + b)*HSZ + j2), "f"(hn) : "memory");
            eobf[((size_t)t*BSZ + b)*HSZ + j2] = __float2bfloat16(0.5f*hn);
        }
        __threadfence();
        __syncthreads();
        if (tid == 0) atomicAdd(&flags[b*MSZ + t], 1);
        if (t < MSZ-1) {
            if (tid == 0) {
                while (((volatile int*)flags)[b*MSZ + t] < 4) {}
            }
            __syncthreads();
            __threadfence();
            if (tid < 64) {
                float4 hv;
                const float* src = hbuf + ((size_t)(t & 1)*BSZ + b)*HSZ + tid*4;
                asm volatile("ld.global.cg.v4.f32 {%0,%1,%2,%3}, [%4];"
                    : "=f"(hv.x), "=f"(hv.y), "=f"(hv.z), "=f"(hv.w) : "l"(src));
                *(float4*)&hsh[tid*4] = hv;
            }
            __syncthreads();
        }
    }
}

// ---------------- decoder pointwise: 4 rows per block, 1024 threads ----------------
__global__ __launch_bounds__(1024)
void dec_point(const float* __restrict__ gates, const float* __restrict__ xg0,
               const float* __restrict__ vxg, const int* __restrict__ x,
               const float* __restrict__ bih, const float* __restrict__ bhh,
               float* __restrict__ cc, __nv_bfloat16* __restrict__ hbf,
               __nv_bfloat16* __restrict__ abf, int t)
{
    int r = blockIdx.x*4 + (threadIdx.x >> 8);
    int j = threadIdx.x & 255;
    int s = r >> 5, b = r & 31;
    const float* base = nullptr;
    if (t == 0) base = xg0 + (size_t)r*G4;
    else {
        int pos = s + t;
        if (pos <= MSZ-1) base = vxg + (size_t)x[b*MSZ + pos]*G4;
    }
    float xi, xf, xgv, xo;
    if (base) { xi = base[j]; xf = base[j+256]; xgv = base[j+512]; xo = base[j+768]; }
    else {     xi = bih[j]+bhh[j]; xf = bih[j+256]+bhh[j+256];
               xgv = bih[j+512]+bhh[j+512]; xo = bih[j+768]+bhh[j+768]; }
    const float* gr = gates + (size_t)r*G4;
    float gi = gr[j] + xi, gf = gr[j+256] + xf, gg = gr[j+512] + xgv, go = gr[j+768] + xo;
    float cp = (t == 0) ? 0.0f : cc[(size_t)r*HSZ + j];
    float cn = sigmoidf(gf)*cp + sigmoidf(gi)*tanhf(gg);
    float hn = sigmoidf(go)*tanhf(cn);
    cc[(size_t)r*HSZ + j] = cn;
    __nv_bfloat16 hb = __float2bfloat16(hn);
    hbf[(size_t)r*HSZ + j] = hb;
    abf[((size_t)t*SB + r)*ESZ + j] = hb;
}

// ================ bf16 mma.sync logits, vocab-split x2 + partial LSE ===
#define SMA    0
#define SMB0   65536
#define SMB1   131072
#define SMBIAS 196608
#define SMRED  212992
#define SMTOT  214016

__global__ __launch_bounds__(256, 1)
void logits_mma(const __nv_bfloat16* __restrict__ abf, const __nv_bfloat16* __restrict__ bbf,
                const float* __restrict__ e2vb, const int* __restrict__ x,
                float* __restrict__ pm, float* __restrict__ ps,
                float* __restrict__ tgtlog, float* __restrict__ eoslog)
{
    extern __shared__ char sm[];
    uint32_t smb = smem_u32(sm);
    int tid = threadIdx.x, wid = tid >> 5, lane = tid & 31;
    int band = wid & 3, half = wid >> 2;
    int m0 = blockIdx.x * 128;
    int vc = blockIdx.y;
    int vbase = vc * VHALF;

    load_tile_async(smb + SMA, abf + (size_t)m0*ESZ, tid);
    CP_COMMIT();
    load_tile_async(smb + SMB0, bbf + (size_t)vbase*ESZ, tid);
    CP_COMMIT();
    load_tile_async(smb + SMB1, bbf + (size_t)(vbase + 128)*ESZ, tid);
    CP_COMMIT();
    float* bias_s = (float*)(sm + SMBIAS);   // bias for this half, indexed [0,2048)
#pragma unroll
    for (int l = 0; l < 8; l++) {
        int i = tid + l*256;
        int v = vbase + i;
        bias_s[i] = (v < VSZ) ? e2vb[v] : 0.0f;
    }

    int vt[4];
    float Mv[4], Sv[4];
#pragma unroll
    for (int sl = 0; sl < 4; sl++) {
        int rl = band*32 + (sl >> 1)*16 + (sl & 1)*8 + (lane >> 2);
        int row = m0 + rl;
        vt[sl] = -1;
        if (row < NROWS) {
            int t = row / SB; int rr = row % SB; int s = rr >> 5; int b = rr & 31;
            if (t < LSEG) { int pos = s + 1 + t; vt[sl] = (pos <= MSZ-1) ? x[b*MSZ + pos] : 0; }
        }
        Mv[sl] = -3.0e38f; Sv[sl] = 0.0f;
    }

    int swz = lane & 7;
    uint32_t aBase[2];
#pragma unroll
    for (int mi = 0; mi < 2; mi++)
        aBase[mi] = smb + SMA + (uint32_t)(band*32 + mi*16 + (lane & 15))*512;
    int hiA = lane >> 4;
    int hiB = (lane >> 3) & 1;
    uint32_t bRow[4];
#pragma unroll
    for (int p = 0; p < 4; p++)
        bRow[p] = (uint32_t)(half*64 + p*16 + ((lane >> 4) & 1)*8 + (lane & 7))*512;

    CP_WAIT1();
    __syncthreads();

    for (int c = 0; c < NCH_H; c++) {
        uint32_t bbase = smb + ((c & 1) ? SMB1 : SMB0);
        float acc[2][8][4];
#pragma unroll
        for (int mi = 0; mi < 2; mi++)
#pragma unroll
            for (int ni = 0; ni < 8; ni++)
#pragma unroll
                for (int k = 0; k < 4; k++) acc[mi][ni][k] = 0.0f;

#pragma unroll
        for (int kb = 0; kb < 16; kb++) {
            uint32_t a[2][4];
#pragma unroll
            for (int mi = 0; mi < 2; mi++) {
                uint32_t addr = aBase[mi] + (uint32_t)(((2*kb + hiA) ^ swz) << 4);
                ldsm4(a[mi][0], a[mi][1], a[mi][2], a[mi][3], addr);
            }
#pragma unroll
            for (int p = 0; p < 4; p++) {
                uint32_t b0, b1, b2, b3;
                uint32_t addr = bbase + bRow[p] + (uint32_t)(((2*kb + hiB) ^ swz) << 4);
                ldsm4(b0, b1, b2, b3, addr);
#pragma unroll
                for (int mi = 0; mi < 2; mi++) {
                    mma16816(acc[mi][2*p    ], a[mi][0], a[mi][1], a[mi][2], a[mi][3], b0, b1);
                    mma16816(acc[mi][2*p + 1], a[mi][0], a[mi][1], a[mi][2], a[mi][3], b2, b3);
                }
            }
        }

        int vloc = c*128 + half*64 + (lane & 3)*2;   // within-half index
#pragma unroll
        for (int sl = 0; sl < 4; sl++) {
            int mi = sl >> 1, hi = sl & 1;
            int rowg = m0 + band*32 + mi*16 + hi*8 + (lane >> 2);
            float gm = -3.0e38f;
            float lv[16];
#pragma unroll
            for (int ni = 0; ni < 8; ni++) {
#pragma unroll
                for (int j = 0; j < 2; j++) {
                    int vl = vloc + ni*8 + j;
                    int v = vbase + vl;
                    float val = acc[mi][ni][hi*2 + j] + bias_s[vl];
                    if (v == vt[sl]) tgtlog[rowg] = val;
                    if (v == 3 && rowg < NROWS) eoslog[rowg] = val;
                    float e = (v < VSZ) ? val : -1.0e30f;
                    lv[ni*2 + j] = e;
                    gm = fmaxf(gm, e);
                }
            }
            float gs = 0.0f;
#pragma unroll
            for (int q = 0; q < 16; q++) gs += __expf(lv[q] - gm);
#pragma unroll
            for (int d = 1; d <= 2; d <<= 1) {
                float m2 = __shfl_xor_sync(0xffffffffu, gm, d);
                float s2 = __shfl_xor_sync(0xffffffffu, gs, d);
                float nm = fmaxf(gm, m2);
                gs = gs*__expf(gm - nm) + s2*__expf(m2 - nm);
                gm = nm;
            }
            float nm = fmaxf(Mv[sl], gm);
            Sv[sl] = Sv[sl]*__expf(Mv[sl] - nm) + gs*__expf(gm - nm);
            Mv[sl] = nm;
        }

        __syncthreads();
        if (c + 2 < NCH_H)
            load_tile_async(smb + ((c & 1) ? SMB1 : SMB0),
                            bbf + (size_t)(vbase + (c + 2)*128)*ESZ, tid);
        CP_COMMIT();
        CP_WAIT1();
        __syncthreads();
    }

    // cross-half-warp merge via smem, then write per-vocab-half partials
    float* smm = (float*)(sm + SMRED);
    float* sms = smm + 128;
    if (half == 0 && (lane & 3) == 0) {
#pragma unroll
        for (int sl = 0; sl < 4; sl++) {
            int rl = band*32 + (sl >> 1)*16 + (sl & 1)*8 + (lane >> 2);
            smm[rl] = Mv[sl]; sms[rl] = Sv[sl];
        }
    }
    __syncthreads();
    if (half == 1 && (lane & 3) == 0) {
#pragma unroll
        for (int sl = 0; sl < 4; sl++) {
            int rl = band*32 + (sl >> 1)*16 + (sl & 1)*8 + (lane >> 2);
            float m2 = smm[rl], s2 = sms[rl];
            float nm = fmaxf(Mv[sl], m2);
            float s = Sv[sl]*__expf(Mv[sl] - nm) + s2*__expf(m2 - nm);
            int rowg = m0 + rl;
            pm[(size_t)vc*NROWS_PAD + rowg] = nm;
            ps[(size_t)vc*NROWS_PAD + rowg] = s;
        }
    }
}

// ---------------- merge vocab-half partials -> final LSE ----------------
__global__ void lse_merge(const float* __restrict__ pm, const float* __restrict__ ps,
                          float* __restrict__ lse)
{
    int r = blockIdx.x*256 + threadIdx.x;
    if (r >= NROWS) return;
    float m = pm[r], s = ps[r];
    float m2 = pm[NROWS_PAD + r], s2 = ps[NROWS_PAD + r];
    if (m2 <= m) { s += s2*__expf(m2 - m); }
    else         { s = s*__expf(m - m2) + s2; m = m2; }
    lse[r] = m + __logf(s);
}

// ---------------- segment log-probs -> logpy table ----------------
__global__ void logpy_kernel(const float* __restrict__ lse, const float* __restrict__ tgtlog,
                             const float* __restrict__ eoslog, const float* __restrict__ issing,
                             float* __restrict__ logpy)
{
    int idx = blockIdx.x*blockDim.x + threadIdx.x;
    if (idx >= (SSEG+1)*BSZ) return;
    int e = idx >> 5, b = idx & 31;
    if (e == 0) {
        logpy[b] = 0.0f;
        for (int k = 1; k < LSEG; k++) logpy[k*BSZ + b] = NEGINF;
        return;
    }
    int s = e - 1;
    int r = s*BSZ + b;
    float cum = 0.0f;
    float is_start = issing[(s+1)*BSZ + b];
    int jlen = SSEG - s; if (jlen > LSEG) jlen = LSEG;
    for (int k = 0; k < LSEG; k++) {
        int rowk = k*SB + r;
        float tlp = tgtlog[rowk] - lse[rowk];
        float segis = ((s+1+k) <= MSZ-1) ? issing[(s+1+k)*BSZ + b] : 0.0f;
        cum += tlp + ((k >= 1) ? segis : 0.0f);
        int rowe = (k+1)*SB + r;
        float eos = eoslog[rowe] - lse[rowe];
        float val = cum + ((k >= 1) ? is_start : 0.0f) + eos;
        if (k >= jlen) val = NEGINF;
        logpy[(e*LSEG + k)*BSZ + b] = val;
    }
}

// ---------------- final DP over segmentations ----------------
__global__ void dp_kernel(const float* __restrict__ logpy, const int* __restrict__ lengths,
                          float* __restrict__ out)
{
    int b = threadIdx.x;
    __shared__ float alph[MSZ-1][BSZ];
    float buf[LSEG] = {0.0f, NEGINF, NEGINF, NEGINF};
    alph[0][b] = 0.0f;
    for (int m = 1; m < MSZ-1; m++) {
        float v[LSEG], mx = -3.0e38f;
#pragma unroll
        for (int k = 0; k < LSEG; k++) {
            int e = m - k;
            float slp = (e >= 1) ? logpy[(e*LSEG + k)*BSZ + b] : NEGINF;
            v[k] = buf[k] + slp;
            mx = fmaxf(mx, v[k]);
        }
        float ssum = 0.0f;
#pragma unroll
        for (int k = 0; k < LSEG; k++) ssum += __expf(v[k]-mx);
        float a = mx + __logf(ssum);
        buf[3] = buf[2]; buf[2] = buf[1]; buf[1] = buf[0]; buf[0] = a;
        alph[m][b] = a;
    }
    int Lb = lengths[b];
    float nll = -alph[Lb-2][b];
    float tlen = (float)Lb;
#pragma unroll
    for (int off = 16; off; off >>= 1) {
        nll  += __shfl_down_sync(0xffffffffu, nll,  off);
        tlen += __shfl_down_sync(0xffffffffu, tlen, off);
    }
    if (b == 0) out[0] = nll / (tlen - 2.0f*BSZ);
}

// ---------------- launch ----------------
extern "C" void kernel_launch(void* const* d_in, const int* in_sizes, int n_in,
                              void* d_out, int out_size)
{
    const int*   x        = (const int*)  d_in[0];
    const int*   lengths  = (const int*)  d_in[1];
    const float* emb      = (const float*)d_in[2];
    const float* e2vb     = (const float*)d_in[3];
    const float* enc_Wih  = (const float*)d_in[4];
    const float* enc_Whh  = (const float*)d_in[5];
    const float* enc_bih  = (const float*)d_in[6];
    const float* enc_bhh  = (const float*)d_in[7];
    const float* enc_h0   = (const float*)d_in[8];
    const float* enc_c0   = (const float*)d_in[9];
    const float* dec_Wih  = (const float*)d_in[10];
    const float* dec_Whh  = (const float*)d_in[11];
    const float* dec_bih  = (const float*)d_in[12];
    const float* dec_bhh  = (const float*)d_in[13];
    const float* dht_W    = (const float*)d_in[14];
    const float* dht_b    = (const float*)d_in[15];
    const float* sos_W    = (const float*)d_in[16];
    const float* sos_b    = (const float*)d_in[17];
    float* out = (float*)d_out;

    float *p_issing, *p_enc_xg, *p_sos, *p_dxg0, *p_vxg, *p_gates, *p_dec_h, *p_dec_c;
    float *p_lse, *p_tgt, *p_eos, *p_logpy, *p_hbuf, *p_pm, *p_ps;
    int *p_flags;
    __nv_bfloat16 *p_ibf, *p_eobf, *p_sosbf, *p_dhbf, *p_abf, *p_bbf;
    __nv_bfloat16 *p_wihe, *p_whhe, *p_wihd, *p_whhd, *p_sosw, *p_dhtw;
    cudaGetSymbolAddress((void**)&p_issing,  g_issing);
    cudaGetSymbolAddress((void**)&p_enc_xg,  g_enc_xg);
    cudaGetSymbolAddress((void**)&p_sos,     g_sos);
    cudaGetSymbolAddress((void**)&p_dxg0,    g_dxg0);
    cudaGetSymbolAddress((void**)&p_vxg,     g_vxg);
    cudaGetSymbolAddress((void**)&p_gates,   g_gates);
    cudaGetSymbolAddress((void**)&p_dec_h,   g_dec_h);
    cudaGetSymbolAddress((void**)&p_dec_c,   g_dec_c);
    cudaGetSymbolAddress((void**)&p_flags,   g_flags);
    cudaGetSymbolAddress((void**)&p_hbuf,    g_hbuf);
    cudaGetSymbolAddress((void**)&p_pm,      g_pm);
    cudaGetSymbolAddress((void**)&p_ps,      g_ps);
    cudaGetSymbolAddress((void**)&p_ibf,     g_ibf);
    cudaGetSymbolAddress((void**)&p_eobf,    g_eobf);
    cudaGetSymbolAddress((void**)&p_sosbf,   g_sosbf);
    cudaGetSymbolAddress((void**)&p_dhbf,    g_dhbf);
    cudaGetSymbolAddress((void**)&p_abf,     g_abf);
    cudaGetSymbolAddress((void**)&p_bbf,     g_bbf);
    cudaGetSymbolAddress((void**)&p_wihe,    g_wihe);
    cudaGetSymbolAddress((void**)&p_whhe,    g_whhe);
    cudaGetSymbolAddress((void**)&p_wihd,    g_wihd);
    cudaGetSymbolAddress((void**)&p_whhd,    g_whhd);
    cudaGetSymbolAddress((void**)&p_sosw,    g_sosw);
    cudaGetSymbolAddress((void**)&p_dhtw,    g_dhtw);
    cudaGetSymbolAddress((void**)&p_lse,     g_lse);
    cudaGetSymbolAddress((void**)&p_tgt,     g_tgtlog);
    cudaGetSymbolAddress((void**)&p_eos,     g_eoslog);
    cudaGetSymbolAddress((void**)&p_logpy,   g_logpy);

    cudaFuncSetAttribute(logits_mma, cudaFuncAttributeMaxDynamicSharedMemorySize, SMTOT);
    cudaFuncSetAttribute(gemm_mma,   cudaFuncAttributeMaxDynamicSharedMemorySize, GM_TOT);

    // 1. embed (bf16) + is_single
    embed_kernel<<<MSZ*BSZ, 64>>>(x, emb, p_ibf, p_issing);
    // 2. emb -> bf16
    cvt_emb<<<VPAD, 256>>>(emb, p_bbf);
    // 3. encoder weight converts + flag reset
    cvt_w1<<<(G4*ESZ + 255)/256, 256>>>(enc_Wih, p_wihe, enc_Whh, p_whhe,
                                        G4*ESZ, p_flags, BSZ*MSZ);
    // 4. decoder/sos/dht weight converts
    cvt_w2<<<(G4*ESZ + 255)/256, 256>>>(dec_Wih, p_wihd, dec_Whh, p_whhd, G4*ESZ,
                                        sos_W, p_sosw, dht_W, p_dhtw, HSZ*ESZ);
    // 5. encoder input gates (tensor core)
    gemm_mma<<<dim3(32, 8), 256, GM_TOT>>>(p_ibf, p_wihe, enc_bih, enc_bhh,
                                           p_enc_xg, nullptr, MSZ*BSZ, G4, 0);
    // 6. encoder recurrence: 4 CTAs per batch element, L1-resident weights
    enc_lstm<<<BSZ*4, 256>>>(p_enc_xg, p_whhe, enc_h0, enc_c0, p_eobf,
                             p_flags, p_hbuf);
    // 7. sos (bf16 out for dxg0)
    gemm_mma<<<dim3(32, 2), 256, GM_TOT>>>(p_eobf, p_sosw, sos_b, nullptr,
                                           p_sos, p_sosbf, SB, HSZ, 0);
    // 8. dec_h0 = tanh(...) (bf16 out)
    gemm_mma<<<dim3(32, 2), 256, GM_TOT>>>(p_eobf, p_dhtw, dht_b, nullptr,
                                           p_dec_h, p_dhbf, SB, HSZ, 1);
    // 9. vocab input gates
    gemm_mma<<<dim3(32, 8), 256, GM_TOT>>>(p_bbf, p_wihd, dec_bih, dec_bhh,
                                           p_vxg, nullptr, VSZ, G4, 0);
    // 10. step-0 input gates from sos
    gemm_mma<<<dim3(32, 8), 256, GM_TOT>>>(p_sosbf, p_wihd, dec_bih, dec_bhh,
                                           p_dxg0, nullptr, SB, G4, 0);
    // 11. decoder: 5 sequential steps
    for (int t = 0; t <= LSEG; t++) {
        gemm_mma<<<dim3(32, 8), 256, GM_TOT>>>(p_dhbf, p_whhd, nullptr, nullptr,
                                               p_gates, nullptr, SB, G4, 2);
        dec_point<<<SB/4, 1024>>>(p_gates, p_dxg0, p_vxg, x, dec_bih, dec_bhh,
                                  p_dec_c, p_dhbf, p_abf, t);
    }
    // 12. bf16 mma.sync logits, vocab-split x2 (316 blocks)
    logits_mma<<<dim3(MTILES, 2), 256, SMTOT>>>(p_abf, p_bbf, e2vb, x,
                                                p_pm, p_ps, p_tgt, p_eos);
    // 13. merge vocab-half partials
    lse_merge<<<(NROWS + 255)/256, 256>>>(p_pm, p_ps, p_lse);
    // 14. segment log-probs table
    logpy_kernel<<<((SSEG+1)*BSZ + 127)/128, 128>>>(p_lse, p_tgt, p_eos, p_issing, p_logpy);
    // 15. DP + reduction -> scalar
    dp_kernel<<<1, 32>>>(p_logpy, lengths, out);

    (void)in_sizes; (void)n_in; (void)out_size;
}